// round 1
// baseline (speedup 1.0000x reference)
#include <cuda_runtime.h>
#include <math.h>

// ---------------- problem constants ----------------
#define BB   2
#define SS   1024
#define DD   2048
#define HH   16
#define KVHH 8
#define HDD  128
#define DFF  8192
#define EE   8
#define RR   16
#define BSN  (BB*SS)          // 2048 tokens
#define SCALING_F 2.0f        // 32/16
#define EPS_F 1e-5f

// ---------------- scratch (device globals; no runtime alloc) ----------------
__device__ float g_h   [BSN*DD];
__device__ float g_tmp [BSN*RR];
__device__ float g_xq  [BSN*HH*HDD];
__device__ float g_xk  [BSN*KVHH*HDD];
__device__ float g_xv  [BSN*KVHH*HDD];
__device__ float g_sc  [(size_t)BB*HH*SS*SS];      // 128 MB scores
__device__ float g_o   [BSN*HH*HDD];
__device__ float g_x2  [BSN*DD];
__device__ float g_sn  [BSN*DD];
__device__ float g_cw1 [(size_t)BSN*DFF];
__device__ float g_cw3 [(size_t)BSN*DFF];
__device__ float g_srw [(size_t)BSN*DFF];
__device__ float g_srs [(size_t)BSN*2*DFF];        // per-slot sr
__device__ float g_hs  [BSN*DD];
__device__ float g_logits[BSN*EE];
__device__ float g_mid1[BSN*EE*RR];
__device__ float g_mid3[BSN*EE*RR];
__device__ float g_mid2[BSN*2*RR];
__device__ float g_wsl [BSN*2];
__device__ int   g_sel [BSN*2];
__device__ int   g_cnt [EE];
__device__ int   g_list[EE*BSN];

// ---------------- small utility kernels ----------------
__global__ void copy_f4(const float4* __restrict__ src, float4* __restrict__ dst, int n) {
    int i = blockIdx.x * blockDim.x + threadIdx.x;
    if (i < n) dst[i] = src[i];
}

__global__ void zero_cnt_kernel() {
    if (threadIdx.x < EE) g_cnt[threadIdx.x] = 0;
}

// rmsnorm: one block per token row
__global__ __launch_bounds__(256) void rmsnorm_kernel(const float* __restrict__ x,
                                                      const float* __restrict__ w,
                                                      float* __restrict__ y) {
    int row = blockIdx.x;
    const float* xr = x + (size_t)row * DD;
    float* yr = y + (size_t)row * DD;
    float ss = 0.f;
    for (int i = threadIdx.x; i < DD; i += 256) { float v = xr[i]; ss += v * v; }
    __shared__ float red[256];
    red[threadIdx.x] = ss; __syncthreads();
    for (int s = 128; s > 0; s >>= 1) {
        if (threadIdx.x < s) red[threadIdx.x] += red[threadIdx.x + s];
        __syncthreads();
    }
    float scale = rsqrtf(red[0] / (float)DD + EPS_F);
    for (int i = threadIdx.x; i < DD; i += 256) yr[i] = xr[i] * scale * w[i];
}

// rope in place; nh heads per token; pair (d, d+64)
__global__ void rope_kernel(float* __restrict__ X, const float* __restrict__ cosb,
                            const float* __restrict__ sinb, int nh, int total) {
    int i = blockIdx.x * blockDim.x + threadIdx.x;
    if (i >= total) return;
    int d = i & 63;
    int rest = i >> 6;
    int hh = rest % nh;
    int bs = rest / nh;
    int s = bs & (SS - 1);
    size_t base = ((size_t)bs * nh + hh) * HDD;
    float x1 = X[base + d];
    float x2 = X[base + d + 64];
    float c1 = cosb[s * HDD + d];
    float c2 = cosb[s * HDD + d + 64];
    float s1 = sinb[s * HDD + d];
    float s2 = sinb[s * HDD + d + 64];
    X[base + d]      = x1 * c1 - x2 * s1;
    X[base + d + 64] = x2 * c2 + x1 * s2;
}

// ---------------- main 128x128x8 SGEMM ----------------
// C[M,N] = (accum ? C : 0) + alpha * A[M,K] @ B[K,N], row-major, dims multiples of tile
__global__ __launch_bounds__(256) void sgemm128(const float* __restrict__ A,
                                                const float* __restrict__ B,
                                                float* __restrict__ C,
                                                int K, int lda, int ldb, int ldc,
                                                float alpha, int accum) {
    __shared__ float As[8][128];
    __shared__ float Bs[8][128];
    int tid = threadIdx.x;
    int brow = blockIdx.y * 128;
    int bcol = blockIdx.x * 128;
    int tr = (tid / 16) * 8;
    int tc = (tid % 16) * 8;
    int arow = tid >> 1;
    int acol = (tid & 1) * 4;
    int brl = tid >> 5;
    int bcl = (tid & 31) * 4;
    const float* Ap = A + (size_t)(brow + arow) * lda + acol;
    const float* Bp = B + (size_t)brl * ldb + bcol + bcl;
    float acc[8][8];
#pragma unroll
    for (int i = 0; i < 8; i++)
#pragma unroll
        for (int j = 0; j < 8; j++) acc[i][j] = 0.f;

    for (int k0 = 0; k0 < K; k0 += 8) {
        float4 av = *(const float4*)(Ap + k0);
        float4 bv = *(const float4*)(Bp + (size_t)k0 * ldb);
        As[acol + 0][arow] = av.x;
        As[acol + 1][arow] = av.y;
        As[acol + 2][arow] = av.z;
        As[acol + 3][arow] = av.w;
        *(float4*)&Bs[brl][bcl] = bv;
        __syncthreads();
#pragma unroll
        for (int kk = 0; kk < 8; kk++) {
            float a0[8], b0[8];
            *(float4*)&a0[0] = *(const float4*)&As[kk][tr];
            *(float4*)&a0[4] = *(const float4*)&As[kk][tr + 4];
            *(float4*)&b0[0] = *(const float4*)&Bs[kk][tc];
            *(float4*)&b0[4] = *(const float4*)&Bs[kk][tc + 4];
#pragma unroll
            for (int i = 0; i < 8; i++)
#pragma unroll
                for (int j = 0; j < 8; j++) acc[i][j] += a0[i] * b0[j];
        }
        __syncthreads();
    }
#pragma unroll
    for (int i = 0; i < 8; i++) {
        float* Cr = C + (size_t)(brow + tr + i) * ldc + bcol + tc;
#pragma unroll
        for (int j4 = 0; j4 < 8; j4 += 4) {
            float4 cv;
            cv.x = alpha * acc[i][j4 + 0];
            cv.y = alpha * acc[i][j4 + 1];
            cv.z = alpha * acc[i][j4 + 2];
            cv.w = alpha * acc[i][j4 + 3];
            if (accum) {
                float4 old = *(const float4*)(Cr + j4);
                cv.x += old.x; cv.y += old.y; cv.z += old.z; cv.w += old.w;
            }
            *(float4*)(Cr + j4) = cv;
        }
    }
}

// ---------------- skinny GEMM (N = 8 or 16) ----------------
// C[row, cOff*batch + col] = A[row,:] @ Bbase[batch][:,col]
template <int NC>
__global__ __launch_bounds__(128) void skinny_gemm(const float* __restrict__ A,
                                                   const float* __restrict__ Bbase,
                                                   float* __restrict__ C,
                                                   int K, int lda, int ldb, int ldc,
                                                   long bstride, int cOff) {
    int row = blockIdx.x;
    int e = blockIdx.y;
    const float* Bp = Bbase + (size_t)e * bstride;
    const float* Ar = A + (size_t)row * lda;
    int tid = threadIdx.x;
    int col = tid % NC;
    int ksub = tid / NC;
    const int KL = 128 / NC;
    float acc = 0.f;
    for (int k = ksub; k < K; k += KL) acc += Ar[k] * Bp[(size_t)k * ldb + col];
    __shared__ float red[128];
    red[tid] = acc; __syncthreads();
    for (int s = KL / 2; s > 0; s >>= 1) {
        if (ksub < s) red[tid] += red[tid + s * NC];
        __syncthreads();
    }
    if (ksub == 0) C[(size_t)row * ldc + (size_t)e * cOff + col] = red[tid];
}

// ---------------- attention ----------------
__global__ __launch_bounds__(256) void attn_scores(const float* __restrict__ xq,
                                                   const float* __restrict__ xk) {
    int bh = blockIdx.z;
    int b = bh / HH, h = bh % HH, kvh = h >> 1;
    int q0 = blockIdx.y * 64, kc0 = blockIdx.x * 64;
    __shared__ float qs[32][64];
    __shared__ float ks[32][64];
    int tid = threadIdx.x;
    int tr = (tid / 16) * 4, tc = (tid % 16) * 4;
    const float* qb = xq + ((size_t)(b * SS + q0) * HH + h) * HDD;
    const float* kb = xk + ((size_t)(b * SS + kc0) * KVHH + kvh) * HDD;
    float acc[4][4];
#pragma unroll
    for (int i = 0; i < 4; i++)
#pragma unroll
        for (int j = 0; j < 4; j++) acc[i][j] = 0.f;

    for (int kk0 = 0; kk0 < HDD; kk0 += 32) {
#pragma unroll
        for (int l = 0; l < 2; l++) {
            int slot = tid + l * 256;
            int r = slot >> 3;
            int c4 = (slot & 7) * 4;
            float4 v = *(const float4*)(qb + (size_t)r * (HH * HDD) + kk0 + c4);
            qs[c4 + 0][r] = v.x; qs[c4 + 1][r] = v.y; qs[c4 + 2][r] = v.z; qs[c4 + 3][r] = v.w;
            float4 w = *(const float4*)(kb + (size_t)r * (KVHH * HDD) + kk0 + c4);
            ks[c4 + 0][r] = w.x; ks[c4 + 1][r] = w.y; ks[c4 + 2][r] = w.z; ks[c4 + 3][r] = w.w;
        }
        __syncthreads();
#pragma unroll
        for (int kk = 0; kk < 32; kk++) {
            float a0[4], b0[4];
            *(float4*)a0 = *(const float4*)&qs[kk][tr];
            *(float4*)b0 = *(const float4*)&ks[kk][tc];
#pragma unroll
            for (int i = 0; i < 4; i++)
#pragma unroll
                for (int j = 0; j < 4; j++) acc[i][j] += a0[i] * b0[j];
        }
        __syncthreads();
    }
    const float scale = 0.08838834764831845f; // 1/sqrt(128)
#pragma unroll
    for (int i = 0; i < 4; i++) {
        int q = q0 + tr + i;
#pragma unroll
        for (int j = 0; j < 4; j++) {
            int k = kc0 + tc + j;
            float v = acc[i][j] * scale + (k > q ? -1000000000.0f : 0.0f);
            g_sc[((size_t)bh * SS + q) * SS + k] = v;
        }
    }
}

__global__ __launch_bounds__(256) void softmax_rows() {
    size_t row = blockIdx.x;
    float* p = g_sc + row * (size_t)SS;
    int tid = threadIdx.x;
    float mx = -3.4e38f;
    float v[4];
#pragma unroll
    for (int l = 0; l < 4; l++) { v[l] = p[tid + l * 256]; mx = fmaxf(mx, v[l]); }
    __shared__ float red[256];
    red[tid] = mx; __syncthreads();
    for (int s = 128; s > 0; s >>= 1) { if (tid < s) red[tid] = fmaxf(red[tid], red[tid + s]); __syncthreads(); }
    mx = red[0]; __syncthreads();
    float sum = 0.f;
#pragma unroll
    for (int l = 0; l < 4; l++) { v[l] = expf(v[l] - mx); sum += v[l]; }
    red[tid] = sum; __syncthreads();
    for (int s = 128; s > 0; s >>= 1) { if (tid < s) red[tid] += red[tid + s]; __syncthreads(); }
    float inv = 1.f / red[0];
#pragma unroll
    for (int l = 0; l < 4; l++) p[tid + l * 256] = v[l] * inv;
}

__global__ __launch_bounds__(256) void attn_av(const float* __restrict__ xv,
                                               float* __restrict__ o) {
    int bh = blockIdx.z;
    int b = bh / HH, h = bh % HH, kvh = h >> 1;
    int q0 = blockIdx.y * 64, d0 = blockIdx.x * 64;
    __shared__ float as_[32][64];
    __shared__ float vs[32][64];
    int tid = threadIdx.x;
    int tr = (tid / 16) * 4, tc = (tid % 16) * 4;
    const float* ab = g_sc + ((size_t)bh * SS + q0) * SS;
    float acc[4][4];
#pragma unroll
    for (int i = 0; i < 4; i++)
#pragma unroll
        for (int j = 0; j < 4; j++) acc[i][j] = 0.f;

    for (int k0 = 0; k0 < SS; k0 += 32) {
#pragma unroll
        for (int l = 0; l < 2; l++) {
            int slot = tid + l * 256;
            // attn tile: 64 q rows x 32 k cols, store transposed
            int r = slot >> 3;
            int c4 = (slot & 7) * 4;
            float4 v = *(const float4*)(ab + (size_t)r * SS + k0 + c4);
            as_[c4 + 0][r] = v.x; as_[c4 + 1][r] = v.y; as_[c4 + 2][r] = v.z; as_[c4 + 3][r] = v.w;
            // v tile: 32 k rows x 64 d cols, natural
            int kr = slot >> 4;
            int dc4 = (slot & 15) * 4;
            float4 w = *(const float4*)(xv + ((size_t)(b * SS + k0 + kr) * KVHH + kvh) * HDD + d0 + dc4);
            *(float4*)&vs[kr][dc4] = w;
        }
        __syncthreads();
#pragma unroll
        for (int kk = 0; kk < 32; kk++) {
            float a0[4], b0[4];
            *(float4*)a0 = *(const float4*)&as_[kk][tr];
            *(float4*)b0 = *(const float4*)&vs[kk][tc];
#pragma unroll
            for (int i = 0; i < 4; i++)
#pragma unroll
                for (int j = 0; j < 4; j++) acc[i][j] += a0[i] * b0[j];
        }
        __syncthreads();
    }
#pragma unroll
    for (int i = 0; i < 4; i++) {
        int q = q0 + tr + i;
#pragma unroll
        for (int j = 0; j < 4; j++)
            o[((size_t)(b * SS + q) * HH + h) * HDD + d0 + tc + j] = acc[i][j];
    }
}

// ---------------- MoE routing ----------------
__global__ void gate_topk() {
    int t = blockIdx.x * blockDim.x + threadIdx.x;
    if (t >= BSN) return;
    float l[EE];
    float mx = -3.4e38f;
#pragma unroll
    for (int e = 0; e < EE; e++) { l[e] = g_logits[t * EE + e]; mx = fmaxf(mx, l[e]); }
    float sum = 0.f;
#pragma unroll
    for (int e = 0; e < EE; e++) { l[e] = expf(l[e] - mx); sum += l[e]; }
#pragma unroll
    for (int e = 0; e < EE; e++) l[e] /= sum;
    int i0 = 0;
#pragma unroll
    for (int e = 1; e < EE; e++) if (l[e] > l[i0]) i0 = e;
    int i1 = (i0 == 0) ? 1 : 0;
#pragma unroll
    for (int e = 0; e < EE; e++) if (e != i0 && l[e] > l[i1]) i1 = e;
    float s2 = l[i0] + l[i1];
    g_wsl[t * 2 + 0] = l[i0] / s2;
    g_wsl[t * 2 + 1] = l[i1] / s2;
    g_sel[t * 2 + 0] = i0;
    g_sel[t * 2 + 1] = i1;
    int p0 = atomicAdd(&g_cnt[i0], 1);
    g_list[i0 * BSN + p0] = t * 2;
    int p1 = atomicAdd(&g_cnt[i1], 1);
    g_list[i1 * BSN + p1] = t * 2 + 1;
}

// per-expert fused SwiGLU + rank-16 LoRA: writes sr per (token, slot)
__global__ __launch_bounds__(256) void expert_kernel(const float* __restrict__ b1,
                                                     const float* __restrict__ b3) {
    int e = blockIdx.y;
    int j0 = blockIdx.x * 256;
    __shared__ float b1s[RR][256];
    __shared__ float b3s[RR][256];
    int tid = threadIdx.x;
#pragma unroll
    for (int r = 0; r < RR; r++) {
        b1s[r][tid] = b1[((size_t)e * RR + r) * DFF + j0 + tid];
        b3s[r][tid] = b3[((size_t)e * RR + r) * DFF + j0 + tid];
    }
    __syncthreads();
    int n = g_cnt[e];
    for (int i = 0; i < n; i++) {
        int ent = g_list[e * BSN + i];
        int t = ent >> 1, slot = ent & 1;
        float x1 = g_cw1[(size_t)t * DFF + j0 + tid];
        float x3 = g_cw3[(size_t)t * DFF + j0 + tid];
        const float* m1 = &g_mid1[(size_t)t * EE * RR + e * RR];
        const float* m3 = &g_mid3[(size_t)t * EE * RR + e * RR];
#pragma unroll
        for (int r = 0; r < RR; r++) {
            x1 += SCALING_F * m1[r] * b1s[r][tid];
            x3 += SCALING_F * m3[r] * b3s[r][tid];
        }
        float sr = x1 / (1.f + expf(-x1)) * x3;
        g_srs[((size_t)t * 2 + slot) * DFF + j0 + tid] = sr;
    }
}

__global__ void combine_srw(int total) {
    int i = blockIdx.x * blockDim.x + threadIdx.x;
    if (i >= total) return;
    int t = i / DFF;
    int j = i % DFF;
    g_srw[(size_t)i] = g_wsl[t * 2 + 0] * g_srs[((size_t)t * 2 + 0) * DFF + j]
                     + g_wsl[t * 2 + 1] * g_srs[((size_t)t * 2 + 1) * DFF + j];
}

// mid2[t,slot,r] = sr_slot[t,slot,:] @ a2[sel][:,r]
__global__ __launch_bounds__(256) void mid2_kernel(const float* __restrict__ a2) {
    int ts = blockIdx.x;
    int t = ts >> 1, slot = ts & 1;
    int e = g_sel[t * 2 + slot];
    const float* sr = g_srs + (size_t)ts * DFF;
    const float* A2 = a2 + (size_t)e * DFF * RR;
    int tid = threadIdx.x;
    int r = tid % RR;
    int jo = tid / RR; // 16 j lanes
    float acc = 0.f;
    for (int j = jo; j < DFF; j += 16) acc += sr[j] * A2[(size_t)j * RR + r];
    __shared__ float red[256];
    red[tid] = acc; __syncthreads();
    for (int s = 8; s > 0; s >>= 1) {
        if (jo < s) red[tid] += red[tid + s * RR];
        __syncthreads();
    }
    if (jo == 0) g_mid2[(size_t)ts * RR + r] = red[tid];
}

// out = x2 + hs + sum_slot wsl*SCALING* mid2 @ b2[sel]
__global__ __launch_bounds__(256) void final_epilogue(const float* __restrict__ b2,
                                                      float* __restrict__ out) {
    int t = blockIdx.x;
    __shared__ float m2s[2][RR];
    __shared__ float ws[2];
    __shared__ int es[2];
    int tid = threadIdx.x;
    if (tid < 32) {
        int slot = tid / RR, r = tid % RR;
        m2s[slot][r] = g_mid2[(size_t)(t * 2 + slot) * RR + r];
    }
    if (tid < 2) { ws[tid] = g_wsl[t * 2 + tid]; es[tid] = g_sel[t * 2 + tid]; }
    __syncthreads();
    for (int d = tid; d < DD; d += 256) {
        float acc = g_x2[(size_t)t * DD + d] + g_hs[(size_t)t * DD + d];
#pragma unroll
        for (int slot = 0; slot < 2; slot++) {
            const float* B2 = b2 + (size_t)es[slot] * RR * DD;
            float c = 0.f;
#pragma unroll
            for (int r = 0; r < RR; r++) c += m2s[slot][r] * B2[(size_t)r * DD + d];
            acc += ws[slot] * SCALING_F * c;
        }
        out[(size_t)t * DD + d] = acc;
    }
}

// ---------------- launch ----------------
extern "C" void kernel_launch(void* const* d_in, const int* in_sizes, int n_in,
                              void* d_out, int out_size) {
    const float* data = (const float*)d_in[0];
    const float* cosb = (const float*)d_in[2];
    const float* sinb = (const float*)d_in[3];
    const float* anw  = (const float*)d_in[4];
    const float* fnw  = (const float*)d_in[5];
    const float* wq   = (const float*)d_in[6];
    const float* wk   = (const float*)d_in[7];
    const float* wv   = (const float*)d_in[8];
    const float* wo   = (const float*)d_in[9];
    const float* qa   = (const float*)d_in[10];
    const float* qb   = (const float*)d_in[11];
    const float* ka   = (const float*)d_in[12];
    const float* kb   = (const float*)d_in[13];
    const float* va   = (const float*)d_in[14];
    const float* vb   = (const float*)d_in[15];
    const float* oa   = (const float*)d_in[16];
    const float* ob   = (const float*)d_in[17];
    const float* gw   = (const float*)d_in[18];
    const float* w1   = (const float*)d_in[19];
    const float* w2   = (const float*)d_in[20];
    const float* w3   = (const float*)d_in[21];
    const float* a1   = (const float*)d_in[22];
    const float* b1   = (const float*)d_in[23];
    const float* a3   = (const float*)d_in[24];
    const float* b3   = (const float*)d_in[25];
    const float* a2   = (const float*)d_in[26];
    const float* b2   = (const float*)d_in[27];
    float* out = (float*)d_out;

    float *p_h, *p_tmp, *p_xq, *p_xk, *p_xv, *p_o, *p_x2, *p_sn;
    float *p_cw1, *p_cw3, *p_srw, *p_hs, *p_logits, *p_mid1, *p_mid3;
    cudaGetSymbolAddress((void**)&p_h,   g_h);
    cudaGetSymbolAddress((void**)&p_tmp, g_tmp);
    cudaGetSymbolAddress((void**)&p_xq,  g_xq);
    cudaGetSymbolAddress((void**)&p_xk,  g_xk);
    cudaGetSymbolAddress((void**)&p_xv,  g_xv);
    cudaGetSymbolAddress((void**)&p_o,   g_o);
    cudaGetSymbolAddress((void**)&p_x2,  g_x2);
    cudaGetSymbolAddress((void**)&p_sn,  g_sn);
    cudaGetSymbolAddress((void**)&p_cw1, g_cw1);
    cudaGetSymbolAddress((void**)&p_cw3, g_cw3);
    cudaGetSymbolAddress((void**)&p_srw, g_srw);
    cudaGetSymbolAddress((void**)&p_hs,  g_hs);
    cudaGetSymbolAddress((void**)&p_logits, g_logits);
    cudaGetSymbolAddress((void**)&p_mid1, g_mid1);
    cudaGetSymbolAddress((void**)&p_mid3, g_mid3);

    // 1. rmsnorm 1
    rmsnorm_kernel<<<BSN, 256>>>(data, anw, p_h);

    // 2. QKV projections + LoRA
    sgemm128<<<dim3(DD/128, BSN/128), 256>>>(p_h, wq, p_xq, DD, DD, DD, DD, 1.f, 0);
    skinny_gemm<16><<<dim3(BSN,1), 128>>>(p_h, qa, p_tmp, DD, DD, RR, RR, 0, 0);
    sgemm128<<<dim3(DD/128, BSN/128), 256>>>(p_tmp, qb, p_xq, RR, RR, DD, DD, SCALING_F, 1);

    sgemm128<<<dim3((KVHH*HDD)/128, BSN/128), 256>>>(p_h, wk, p_xk, DD, DD, KVHH*HDD, KVHH*HDD, 1.f, 0);
    skinny_gemm<16><<<dim3(BSN,1), 128>>>(p_h, ka, p_tmp, DD, DD, RR, RR, 0, 0);
    sgemm128<<<dim3((KVHH*HDD)/128, BSN/128), 256>>>(p_tmp, kb, p_xk, RR, RR, KVHH*HDD, KVHH*HDD, SCALING_F, 1);

    sgemm128<<<dim3((KVHH*HDD)/128, BSN/128), 256>>>(p_h, wv, p_xv, DD, DD, KVHH*HDD, KVHH*HDD, 1.f, 0);
    skinny_gemm<16><<<dim3(BSN,1), 128>>>(p_h, va, p_tmp, DD, DD, RR, RR, 0, 0);
    sgemm128<<<dim3((KVHH*HDD)/128, BSN/128), 256>>>(p_tmp, vb, p_xv, RR, RR, KVHH*HDD, KVHH*HDD, SCALING_F, 1);

    // 3. RoPE
    rope_kernel<<<(BSN*HH*64 + 255)/256, 256>>>(p_xq, cosb, sinb, HH, BSN*HH*64);
    rope_kernel<<<(BSN*KVHH*64 + 255)/256, 256>>>(p_xk, cosb, sinb, KVHH, BSN*KVHH*64);

    // 4. attention
    attn_scores<<<dim3(SS/64, SS/64, BB*HH), 256>>>(p_xq, p_xk);
    softmax_rows<<<BB*HH*SS, 256>>>();
    attn_av<<<dim3(HDD/64, SS/64, BB*HH), 256>>>(p_xv, p_o);

    // 5. output projection + LoRA + residual
    copy_f4<<<(BSN*DD/4 + 255)/256, 256>>>((const float4*)data, (float4*)p_x2, BSN*DD/4);
    sgemm128<<<dim3(DD/128, BSN/128), 256>>>(p_o, wo, p_x2, HH*HDD, HH*HDD, DD, DD, 1.f, 1);
    skinny_gemm<16><<<dim3(BSN,1), 128>>>(p_o, oa, p_tmp, HH*HDD, HH*HDD, RR, RR, 0, 0);
    sgemm128<<<dim3(DD/128, BSN/128), 256>>>(p_tmp, ob, p_x2, RR, RR, DD, DD, SCALING_F, 1);

    // 6. rmsnorm 2
    rmsnorm_kernel<<<BSN, 256>>>(p_x2, fnw, p_sn);

    // 7. shared FFN GEMMs
    sgemm128<<<dim3(DFF/128, BSN/128), 256>>>(p_sn, w1, p_cw1, DD, DD, DFF, DFF, 1.f, 0);
    sgemm128<<<dim3(DFF/128, BSN/128), 256>>>(p_sn, w3, p_cw3, DD, DD, DFF, DFF, 1.f, 0);

    // 8. gating
    skinny_gemm<8><<<dim3(BSN,1), 128>>>(p_sn, gw, p_logits, DD, DD, EE, EE, 0, 0);
    zero_cnt_kernel<<<1, 32>>>();
    gate_topk<<<(BSN + 255)/256, 256>>>();

    // 9. per-expert LoRA mids (all experts, cheap)
    skinny_gemm<16><<<dim3(BSN, EE), 128>>>(p_sn, a1, p_mid1, DD, DD, RR, EE*RR, (long)DD*RR, RR);
    skinny_gemm<16><<<dim3(BSN, EE), 128>>>(p_sn, a3, p_mid3, DD, DD, RR, EE*RR, (long)DD*RR, RR);

    // 10. fused expert SwiGLU (selected tokens only)
    expert_kernel<<<dim3(DFF/256, EE), 256>>>(b1, b3);

    // 11. weighted combine + shared w2 GEMM
    combine_srw<<<(BSN*DFF + 255)/256, 256>>>(BSN*DFF);
    sgemm128<<<dim3(DD/128, BSN/128), 256>>>(p_srw, w2, p_hs, DFF, DFF, DD, DD, 1.f, 0);

    // 12. lora2 mids + final epilogue
    mid2_kernel<<<BSN*2, 256>>>(a2);
    final_epilogue<<<BSN, 256>>>(b2, out);
}

// round 2
// speedup vs baseline: 1.0064x; 1.0064x over previous
#include <cuda_runtime.h>
#include <math.h>

// ---------------- problem constants ----------------
#define BB   2
#define SS   1024
#define DD   2048
#define HH   16
#define KVHH 8
#define HDD  128
#define DFF  8192
#define EE   8
#define RR   16
#define BSN  (BB*SS)          // 2048 tokens
#define SCALING_F 2.0f        // 32/16
#define EPS_F 1e-5f

// ---------------- scratch (device globals; no runtime alloc) ----------------
__device__ float g_h   [BSN*DD];
__device__ float g_tmp [BSN*RR];
__device__ float g_xq  [BSN*HH*HDD];
__device__ float g_xk  [BSN*KVHH*HDD];
__device__ float g_xv  [BSN*KVHH*HDD];
__device__ float g_sc  [(size_t)BB*HH*SS*SS];      // 128 MB scores
__device__ float g_o   [BSN*HH*HDD];
__device__ float g_x2  [BSN*DD];
__device__ float g_sn  [BSN*DD];
__device__ float g_cw1 [(size_t)BSN*DFF];
__device__ float g_cw3 [(size_t)BSN*DFF];
__device__ float g_srw [(size_t)BSN*DFF];
__device__ float g_srs [(size_t)BSN*2*DFF];        // per-slot sr
__device__ float g_hs  [BSN*DD];
__device__ float g_logits[BSN*EE];
__device__ float g_mid1[BSN*EE*RR];
__device__ float g_mid3[BSN*EE*RR];
__device__ float g_mid2[BSN*2*RR];
__device__ float g_wsl [BSN*2];
__device__ int   g_sel [BSN*2];
__device__ int   g_cnt [EE];
__device__ int   g_list[EE*BSN];

// ---------------- small utility kernels ----------------
__global__ void copy_f4(const float4* __restrict__ src, float4* __restrict__ dst, int n) {
    int i = blockIdx.x * blockDim.x + threadIdx.x;
    if (i < n) dst[i] = src[i];
}

__global__ void zero_cnt_kernel() {
    if (threadIdx.x < EE) g_cnt[threadIdx.x] = 0;
}

// rmsnorm: one block per token row
__global__ __launch_bounds__(256) void rmsnorm_kernel(const float* __restrict__ x,
                                                      const float* __restrict__ w,
                                                      float* __restrict__ y) {
    int row = blockIdx.x;
    const float* xr = x + (size_t)row * DD;
    float* yr = y + (size_t)row * DD;
    float ss = 0.f;
    for (int i = threadIdx.x; i < DD; i += 256) { float v = xr[i]; ss += v * v; }
    __shared__ float red[256];
    red[threadIdx.x] = ss; __syncthreads();
    for (int s = 128; s > 0; s >>= 1) {
        if (threadIdx.x < s) red[threadIdx.x] += red[threadIdx.x + s];
        __syncthreads();
    }
    float scale = rsqrtf(red[0] / (float)DD + EPS_F);
    for (int i = threadIdx.x; i < DD; i += 256) yr[i] = xr[i] * scale * w[i];
}

// rope in place; nh heads per token; pair (d, d+64)
__global__ void rope_kernel(float* __restrict__ X, const float* __restrict__ cosb,
                            const float* __restrict__ sinb, int nh, int total) {
    int i = blockIdx.x * blockDim.x + threadIdx.x;
    if (i >= total) return;
    int d = i & 63;
    int rest = i >> 6;
    int hh = rest % nh;
    int bs = rest / nh;
    int s = bs & (SS - 1);
    size_t base = ((size_t)bs * nh + hh) * HDD;
    float x1 = X[base + d];
    float x2 = X[base + d + 64];
    float c1 = cosb[s * HDD + d];
    float c2 = cosb[s * HDD + d + 64];
    float s1 = sinb[s * HDD + d];
    float s2 = sinb[s * HDD + d + 64];
    X[base + d]      = x1 * c1 - x2 * s1;
    X[base + d + 64] = x2 * c2 + x1 * s2;
}

// ---------------- main 128x128x8 SGEMM ----------------
// C[M,N] = (accum ? C : 0) + alpha * A[M,K] @ B[K,N], row-major, dims multiples of tile
__global__ __launch_bounds__(256) void sgemm128(const float* __restrict__ A,
                                                const float* __restrict__ B,
                                                float* __restrict__ C,
                                                int K, int lda, int ldb, int ldc,
                                                float alpha, int accum) {
    __shared__ float As[8][128];
    __shared__ float Bs[8][128];
    int tid = threadIdx.x;
    int brow = blockIdx.y * 128;
    int bcol = blockIdx.x * 128;
    int tr = (tid / 16) * 8;
    int tc = (tid % 16) * 8;
    int arow = tid >> 1;
    int acol = (tid & 1) * 4;
    int brl = tid >> 5;
    int bcl = (tid & 31) * 4;
    const float* Ap = A + (size_t)(brow + arow) * lda + acol;
    const float* Bp = B + (size_t)brl * ldb + bcol + bcl;
    float acc[8][8];
#pragma unroll
    for (int i = 0; i < 8; i++)
#pragma unroll
        for (int j = 0; j < 8; j++) acc[i][j] = 0.f;

    for (int k0 = 0; k0 < K; k0 += 8) {
        float4 av = *(const float4*)(Ap + k0);
        float4 bv = *(const float4*)(Bp + (size_t)k0 * ldb);
        As[acol + 0][arow] = av.x;
        As[acol + 1][arow] = av.y;
        As[acol + 2][arow] = av.z;
        As[acol + 3][arow] = av.w;
        *(float4*)&Bs[brl][bcl] = bv;
        __syncthreads();
#pragma unroll
        for (int kk = 0; kk < 8; kk++) {
            float a0[8], b0[8];
            *(float4*)&a0[0] = *(const float4*)&As[kk][tr];
            *(float4*)&a0[4] = *(const float4*)&As[kk][tr + 4];
            *(float4*)&b0[0] = *(const float4*)&Bs[kk][tc];
            *(float4*)&b0[4] = *(const float4*)&Bs[kk][tc + 4];
#pragma unroll
            for (int i = 0; i < 8; i++)
#pragma unroll
                for (int j = 0; j < 8; j++) acc[i][j] += a0[i] * b0[j];
        }
        __syncthreads();
    }
#pragma unroll
    for (int i = 0; i < 8; i++) {
        float* Cr = C + (size_t)(brow + tr + i) * ldc + bcol + tc;
#pragma unroll
        for (int j4 = 0; j4 < 8; j4 += 4) {
            float4 cv;
            cv.x = alpha * acc[i][j4 + 0];
            cv.y = alpha * acc[i][j4 + 1];
            cv.z = alpha * acc[i][j4 + 2];
            cv.w = alpha * acc[i][j4 + 3];
            if (accum) {
                float4 old = *(const float4*)(Cr + j4);
                cv.x += old.x; cv.y += old.y; cv.z += old.z; cv.w += old.w;
            }
            *(float4*)(Cr + j4) = cv;
        }
    }
}

// ---------------- skinny GEMM (N = 8 or 16) ----------------
// C[row, cOff*batch + col] = A[row,:] @ Bbase[batch][:,col]
template <int NC>
__global__ __launch_bounds__(128) void skinny_gemm(const float* __restrict__ A,
                                                   const float* __restrict__ Bbase,
                                                   float* __restrict__ C,
                                                   int K, int lda, int ldb, int ldc,
                                                   long bstride, int cOff) {
    int row = blockIdx.x;
    int e = blockIdx.y;
    const float* Bp = Bbase + (size_t)e * bstride;
    const float* Ar = A + (size_t)row * lda;
    int tid = threadIdx.x;
    int col = tid % NC;
    int ksub = tid / NC;
    const int KL = 128 / NC;
    float acc = 0.f;
    for (int k = ksub; k < K; k += KL) acc += Ar[k] * Bp[(size_t)k * ldb + col];
    __shared__ float red[128];
    red[tid] = acc; __syncthreads();
    for (int s = KL / 2; s > 0; s >>= 1) {
        if (ksub < s) red[tid] += red[tid + s * NC];
        __syncthreads();
    }
    if (ksub == 0) C[(size_t)row * ldc + (size_t)e * cOff + col] = red[tid];
}

// ---------------- attention ----------------
__global__ __launch_bounds__(256) void attn_scores(const float* __restrict__ xq,
                                                   const float* __restrict__ xk) {
    int bh = blockIdx.z;
    int b = bh / HH, h = bh % HH, kvh = h >> 1;
    int q0 = blockIdx.y * 64, kc0 = blockIdx.x * 64;
    __shared__ float qs[32][64];
    __shared__ float ks[32][64];
    int tid = threadIdx.x;
    int tr = (tid / 16) * 4, tc = (tid % 16) * 4;
    const float* qb = xq + ((size_t)(b * SS + q0) * HH + h) * HDD;
    const float* kb = xk + ((size_t)(b * SS + kc0) * KVHH + kvh) * HDD;
    float acc[4][4];
#pragma unroll
    for (int i = 0; i < 4; i++)
#pragma unroll
        for (int j = 0; j < 4; j++) acc[i][j] = 0.f;

    for (int kk0 = 0; kk0 < HDD; kk0 += 32) {
#pragma unroll
        for (int l = 0; l < 2; l++) {
            int slot = tid + l * 256;
            int r = slot >> 3;
            int c4 = (slot & 7) * 4;
            float4 v = *(const float4*)(qb + (size_t)r * (HH * HDD) + kk0 + c4);
            qs[c4 + 0][r] = v.x; qs[c4 + 1][r] = v.y; qs[c4 + 2][r] = v.z; qs[c4 + 3][r] = v.w;
            float4 w = *(const float4*)(kb + (size_t)r * (KVHH * HDD) + kk0 + c4);
            ks[c4 + 0][r] = w.x; ks[c4 + 1][r] = w.y; ks[c4 + 2][r] = w.z; ks[c4 + 3][r] = w.w;
        }
        __syncthreads();
#pragma unroll
        for (int kk = 0; kk < 32; kk++) {
            float a0[4], b0[4];
            *(float4*)a0 = *(const float4*)&qs[kk][tr];
            *(float4*)b0 = *(const float4*)&ks[kk][tc];
#pragma unroll
            for (int i = 0; i < 4; i++)
#pragma unroll
                for (int j = 0; j < 4; j++) acc[i][j] += a0[i] * b0[j];
        }
        __syncthreads();
    }
    const float scale = 0.08838834764831845f; // 1/sqrt(128)
#pragma unroll
    for (int i = 0; i < 4; i++) {
        int q = q0 + tr + i;
#pragma unroll
        for (int j = 0; j < 4; j++) {
            int k = kc0 + tc + j;
            float v = acc[i][j] * scale + (k > q ? -1000000000.0f : 0.0f);
            g_sc[((size_t)bh * SS + q) * SS + k] = v;
        }
    }
}

__global__ __launch_bounds__(256) void softmax_rows() {
    size_t row = blockIdx.x;
    float* p = g_sc + row * (size_t)SS;
    int tid = threadIdx.x;
    float mx = -3.4e38f;
    float v[4];
#pragma unroll
    for (int l = 0; l < 4; l++) { v[l] = p[tid + l * 256]; mx = fmaxf(mx, v[l]); }
    __shared__ float red[256];
    red[tid] = mx; __syncthreads();
    for (int s = 128; s > 0; s >>= 1) { if (tid < s) red[tid] = fmaxf(red[tid], red[tid + s]); __syncthreads(); }
    mx = red[0]; __syncthreads();
    float sum = 0.f;
#pragma unroll
    for (int l = 0; l < 4; l++) { v[l] = expf(v[l] - mx); sum += v[l]; }
    red[tid] = sum; __syncthreads();
    for (int s = 128; s > 0; s >>= 1) { if (tid < s) red[tid] += red[tid + s]; __syncthreads(); }
    float inv = 1.f / red[0];
#pragma unroll
    for (int l = 0; l < 4; l++) p[tid + l * 256] = v[l] * inv;
}

__global__ __launch_bounds__(256) void attn_av(const float* __restrict__ xv,
                                               float* __restrict__ o) {
    int bh = blockIdx.z;
    int b = bh / HH, h = bh % HH, kvh = h >> 1;
    int q0 = blockIdx.y * 64, d0 = blockIdx.x * 64;
    __shared__ float as_[32][64];
    __shared__ float vs[32][64];
    int tid = threadIdx.x;
    int tr = (tid / 16) * 4, tc = (tid % 16) * 4;
    const float* ab = g_sc + ((size_t)bh * SS + q0) * SS;
    float acc[4][4];
#pragma unroll
    for (int i = 0; i < 4; i++)
#pragma unroll
        for (int j = 0; j < 4; j++) acc[i][j] = 0.f;

    for (int k0 = 0; k0 < SS; k0 += 32) {
#pragma unroll
        for (int l = 0; l < 2; l++) {
            int slot = tid + l * 256;
            // attn tile: 64 q rows x 32 k cols, store transposed
            int r = slot >> 3;
            int c4 = (slot & 7) * 4;
            float4 v = *(const float4*)(ab + (size_t)r * SS + k0 + c4);
            as_[c4 + 0][r] = v.x; as_[c4 + 1][r] = v.y; as_[c4 + 2][r] = v.z; as_[c4 + 3][r] = v.w;
            // v tile: 32 k rows x 64 d cols, natural
            int kr = slot >> 4;
            int dc4 = (slot & 15) * 4;
            float4 w = *(const float4*)(xv + ((size_t)(b * SS + k0 + kr) * KVHH + kvh) * HDD + d0 + dc4);
            *(float4*)&vs[kr][dc4] = w;
        }
        __syncthreads();
#pragma unroll
        for (int kk = 0; kk < 32; kk++) {
            float a0[4], b0[4];
            *(float4*)a0 = *(const float4*)&as_[kk][tr];
            *(float4*)b0 = *(const float4*)&vs[kk][tc];
#pragma unroll
            for (int i = 0; i < 4; i++)
#pragma unroll
                for (int j = 0; j < 4; j++) acc[i][j] += a0[i] * b0[j];
        }
        __syncthreads();
    }
#pragma unroll
    for (int i = 0; i < 4; i++) {
        int q = q0 + tr + i;
#pragma unroll
        for (int j = 0; j < 4; j++)
            o[((size_t)(b * SS + q) * HH + h) * HDD + d0 + tc + j] = acc[i][j];
    }
}

// ---------------- MoE routing ----------------
__global__ void gate_topk() {
    int t = blockIdx.x * blockDim.x + threadIdx.x;
    if (t >= BSN) return;
    float l[EE];
    float mx = -3.4e38f;
#pragma unroll
    for (int e = 0; e < EE; e++) { l[e] = g_logits[t * EE + e]; mx = fmaxf(mx, l[e]); }
    float sum = 0.f;
#pragma unroll
    for (int e = 0; e < EE; e++) { l[e] = expf(l[e] - mx); sum += l[e]; }
#pragma unroll
    for (int e = 0; e < EE; e++) l[e] /= sum;
    int i0 = 0;
#pragma unroll
    for (int e = 1; e < EE; e++) if (l[e] > l[i0]) i0 = e;
    int i1 = (i0 == 0) ? 1 : 0;
#pragma unroll
    for (int e = 0; e < EE; e++) if (e != i0 && l[e] > l[i1]) i1 = e;
    float s2 = l[i0] + l[i1];
    g_wsl[t * 2 + 0] = l[i0] / s2;
    g_wsl[t * 2 + 1] = l[i1] / s2;
    g_sel[t * 2 + 0] = i0;
    g_sel[t * 2 + 1] = i1;
    int p0 = atomicAdd(&g_cnt[i0], 1);
    g_list[i0 * BSN + p0] = t * 2;
    int p1 = atomicAdd(&g_cnt[i1], 1);
    g_list[i1 * BSN + p1] = t * 2 + 1;
}

// per-expert fused SwiGLU + rank-16 LoRA: writes sr per (token, slot)
__global__ __launch_bounds__(256) void expert_kernel(const float* __restrict__ b1,
                                                     const float* __restrict__ b3) {
    int e = blockIdx.y;
    int j0 = blockIdx.x * 256;
    __shared__ float b1s[RR][256];
    __shared__ float b3s[RR][256];
    int tid = threadIdx.x;
#pragma unroll
    for (int r = 0; r < RR; r++) {
        b1s[r][tid] = b1[((size_t)e * RR + r) * DFF + j0 + tid];
        b3s[r][tid] = b3[((size_t)e * RR + r) * DFF + j0 + tid];
    }
    __syncthreads();
    int n = g_cnt[e];
    for (int i = 0; i < n; i++) {
        int ent = g_list[e * BSN + i];
        int t = ent >> 1, slot = ent & 1;
        float x1 = g_cw1[(size_t)t * DFF + j0 + tid];
        float x3 = g_cw3[(size_t)t * DFF + j0 + tid];
        const float* m1 = &g_mid1[(size_t)t * EE * RR + e * RR];
        const float* m3 = &g_mid3[(size_t)t * EE * RR + e * RR];
#pragma unroll
        for (int r = 0; r < RR; r++) {
            x1 += SCALING_F * m1[r] * b1s[r][tid];
            x3 += SCALING_F * m3[r] * b3s[r][tid];
        }
        float sr = x1 / (1.f + expf(-x1)) * x3;
        g_srs[((size_t)t * 2 + slot) * DFF + j0 + tid] = sr;
    }
}

__global__ void combine_srw(int total) {
    int i = blockIdx.x * blockDim.x + threadIdx.x;
    if (i >= total) return;
    int t = i / DFF;
    int j = i % DFF;
    g_srw[(size_t)i] = g_wsl[t * 2 + 0] * g_srs[((size_t)t * 2 + 0) * DFF + j]
                     + g_wsl[t * 2 + 1] * g_srs[((size_t)t * 2 + 1) * DFF + j];
}

// mid2[t,slot,r] = sr_slot[t,slot,:] @ a2[sel][:,r]
__global__ __launch_bounds__(256) void mid2_kernel(const float* __restrict__ a2) {
    int ts = blockIdx.x;
    int t = ts >> 1, slot = ts & 1;
    int e = g_sel[t * 2 + slot];
    const float* sr = g_srs + (size_t)ts * DFF;
    const float* A2 = a2 + (size_t)e * DFF * RR;
    int tid = threadIdx.x;
    int r = tid % RR;
    int jo = tid / RR; // 16 j lanes
    float acc = 0.f;
    for (int j = jo; j < DFF; j += 16) acc += sr[j] * A2[(size_t)j * RR + r];
    __shared__ float red[256];
    red[tid] = acc; __syncthreads();
    for (int s = 8; s > 0; s >>= 1) {
        if (jo < s) red[tid] += red[tid + s * RR];
        __syncthreads();
    }
    if (jo == 0) g_mid2[(size_t)ts * RR + r] = red[tid];
}

// out = x2 + hs + sum_slot wsl*SCALING* mid2 @ b2[sel]
__global__ __launch_bounds__(256) void final_epilogue(const float* __restrict__ b2,
                                                      float* __restrict__ out) {
    int t = blockIdx.x;
    __shared__ float m2s[2][RR];
    __shared__ float ws[2];
    __shared__ int es[2];
    int tid = threadIdx.x;
    if (tid < 32) {
        int slot = tid / RR, r = tid % RR;
        m2s[slot][r] = g_mid2[(size_t)(t * 2 + slot) * RR + r];
    }
    if (tid < 2) { ws[tid] = g_wsl[t * 2 + tid]; es[tid] = g_sel[t * 2 + tid]; }
    __syncthreads();
    for (int d = tid; d < DD; d += 256) {
        float acc = g_x2[(size_t)t * DD + d] + g_hs[(size_t)t * DD + d];
#pragma unroll
        for (int slot = 0; slot < 2; slot++) {
            const float* B2 = b2 + (size_t)es[slot] * RR * DD;
            float c = 0.f;
#pragma unroll
            for (int r = 0; r < RR; r++) c += m2s[slot][r] * B2[(size_t)r * DD + d];
            acc += ws[slot] * SCALING_F * c;
        }
        out[(size_t)t * DD + d] = acc;
    }
}

// ---------------- launch ----------------
extern "C" void kernel_launch(void* const* d_in, const int* in_sizes, int n_in,
                              void* d_out, int out_size) {
    const float* data = (const float*)d_in[0];
    const float* cosb = (const float*)d_in[2];
    const float* sinb = (const float*)d_in[3];
    const float* anw  = (const float*)d_in[4];
    const float* fnw  = (const float*)d_in[5];
    const float* wq   = (const float*)d_in[6];
    const float* wk   = (const float*)d_in[7];
    const float* wv   = (const float*)d_in[8];
    const float* wo   = (const float*)d_in[9];
    const float* qa   = (const float*)d_in[10];
    const float* qb   = (const float*)d_in[11];
    const float* ka   = (const float*)d_in[12];
    const float* kb   = (const float*)d_in[13];
    const float* va   = (const float*)d_in[14];
    const float* vb   = (const float*)d_in[15];
    const float* oa   = (const float*)d_in[16];
    const float* ob   = (const float*)d_in[17];
    const float* gw   = (const float*)d_in[18];
    const float* w1   = (const float*)d_in[19];
    const float* w2   = (const float*)d_in[20];
    const float* w3   = (const float*)d_in[21];
    const float* a1   = (const float*)d_in[22];
    const float* b1   = (const float*)d_in[23];
    const float* a3   = (const float*)d_in[24];
    const float* b3   = (const float*)d_in[25];
    const float* a2   = (const float*)d_in[26];
    const float* b2   = (const float*)d_in[27];
    float* out = (float*)d_out;

    float *p_h, *p_tmp, *p_xq, *p_xk, *p_xv, *p_o, *p_x2, *p_sn;
    float *p_cw1, *p_cw3, *p_srw, *p_hs, *p_logits, *p_mid1, *p_mid3;
    cudaGetSymbolAddress((void**)&p_h,   g_h);
    cudaGetSymbolAddress((void**)&p_tmp, g_tmp);
    cudaGetSymbolAddress((void**)&p_xq,  g_xq);
    cudaGetSymbolAddress((void**)&p_xk,  g_xk);
    cudaGetSymbolAddress((void**)&p_xv,  g_xv);
    cudaGetSymbolAddress((void**)&p_o,   g_o);
    cudaGetSymbolAddress((void**)&p_x2,  g_x2);
    cudaGetSymbolAddress((void**)&p_sn,  g_sn);
    cudaGetSymbolAddress((void**)&p_cw1, g_cw1);
    cudaGetSymbolAddress((void**)&p_cw3, g_cw3);
    cudaGetSymbolAddress((void**)&p_srw, g_srw);
    cudaGetSymbolAddress((void**)&p_hs,  g_hs);
    cudaGetSymbolAddress((void**)&p_logits, g_logits);
    cudaGetSymbolAddress((void**)&p_mid1, g_mid1);
    cudaGetSymbolAddress((void**)&p_mid3, g_mid3);

    // 1. rmsnorm 1
    rmsnorm_kernel<<<BSN, 256>>>(data, anw, p_h);

    // 2. QKV projections + LoRA
    sgemm128<<<dim3(DD/128, BSN/128), 256>>>(p_h, wq, p_xq, DD, DD, DD, DD, 1.f, 0);
    skinny_gemm<16><<<dim3(BSN,1), 128>>>(p_h, qa, p_tmp, DD, DD, RR, RR, 0, 0);
    sgemm128<<<dim3(DD/128, BSN/128), 256>>>(p_tmp, qb, p_xq, RR, RR, DD, DD, SCALING_F, 1);

    sgemm128<<<dim3((KVHH*HDD)/128, BSN/128), 256>>>(p_h, wk, p_xk, DD, DD, KVHH*HDD, KVHH*HDD, 1.f, 0);
    skinny_gemm<16><<<dim3(BSN,1), 128>>>(p_h, ka, p_tmp, DD, DD, RR, RR, 0, 0);
    sgemm128<<<dim3((KVHH*HDD)/128, BSN/128), 256>>>(p_tmp, kb, p_xk, RR, RR, KVHH*HDD, KVHH*HDD, SCALING_F, 1);

    sgemm128<<<dim3((KVHH*HDD)/128, BSN/128), 256>>>(p_h, wv, p_xv, DD, DD, KVHH*HDD, KVHH*HDD, 1.f, 0);
    skinny_gemm<16><<<dim3(BSN,1), 128>>>(p_h, va, p_tmp, DD, DD, RR, RR, 0, 0);
    sgemm128<<<dim3((KVHH*HDD)/128, BSN/128), 256>>>(p_tmp, vb, p_xv, RR, RR, KVHH*HDD, KVHH*HDD, SCALING_F, 1);

    // 3. RoPE
    rope_kernel<<<(BSN*HH*64 + 255)/256, 256>>>(p_xq, cosb, sinb, HH, BSN*HH*64);
    rope_kernel<<<(BSN*KVHH*64 + 255)/256, 256>>>(p_xk, cosb, sinb, KVHH, BSN*KVHH*64);

    // 4. attention
    attn_scores<<<dim3(SS/64, SS/64, BB*HH), 256>>>(p_xq, p_xk);
    softmax_rows<<<BB*HH*SS, 256>>>();
    attn_av<<<dim3(HDD/64, SS/64, BB*HH), 256>>>(p_xv, p_o);

    // 5. output projection + LoRA + residual
    copy_f4<<<(BSN*DD/4 + 255)/256, 256>>>((const float4*)data, (float4*)p_x2, BSN*DD/4);
    sgemm128<<<dim3(DD/128, BSN/128), 256>>>(p_o, wo, p_x2, HH*HDD, HH*HDD, DD, DD, 1.f, 1);
    skinny_gemm<16><<<dim3(BSN,1), 128>>>(p_o, oa, p_tmp, HH*HDD, HH*HDD, RR, RR, 0, 0);
    sgemm128<<<dim3(DD/128, BSN/128), 256>>>(p_tmp, ob, p_x2, RR, RR, DD, DD, SCALING_F, 1);

    // 6. rmsnorm 2
    rmsnorm_kernel<<<BSN, 256>>>(p_x2, fnw, p_sn);

    // 7. shared FFN GEMMs
    sgemm128<<<dim3(DFF/128, BSN/128), 256>>>(p_sn, w1, p_cw1, DD, DD, DFF, DFF, 1.f, 0);
    sgemm128<<<dim3(DFF/128, BSN/128), 256>>>(p_sn, w3, p_cw3, DD, DD, DFF, DFF, 1.f, 0);

    // 8. gating
    skinny_gemm<8><<<dim3(BSN,1), 128>>>(p_sn, gw, p_logits, DD, DD, EE, EE, 0, 0);
    zero_cnt_kernel<<<1, 32>>>();
    gate_topk<<<(BSN + 255)/256, 256>>>();

    // 9. per-expert LoRA mids (all experts, cheap)
    skinny_gemm<16><<<dim3(BSN, EE), 128>>>(p_sn, a1, p_mid1, DD, DD, RR, EE*RR, (long)DD*RR, RR);
    skinny_gemm<16><<<dim3(BSN, EE), 128>>>(p_sn, a3, p_mid3, DD, DD, RR, EE*RR, (long)DD*RR, RR);

    // 10. fused expert SwiGLU (selected tokens only)
    expert_kernel<<<dim3(DFF/256, EE), 256>>>(b1, b3);

    // 11. weighted combine + shared w2 GEMM
    combine_srw<<<(BSN*DFF + 255)/256, 256>>>(BSN*DFF);
    sgemm128<<<dim3(DD/128, BSN/128), 256>>>(p_srw, w2, p_hs, DFF, DFF, DD, DD, 1.f, 0);

    // 12. lora2 mids + final epilogue
    mid2_kernel<<<BSN*2, 256>>>(a2);
    final_epilogue<<<BSN, 256>>>(b2, out);
}

// round 3
// speedup vs baseline: 1.0079x; 1.0015x over previous
#include <cuda_runtime.h>
#include <math.h>

// ---------------- problem constants ----------------
#define BB   2
#define SS   1024
#define DD   2048
#define HH   16
#define KVHH 8
#define HDD  128
#define DFF  8192
#define EE   8
#define RR   16
#define BSN  (BB*SS)          // 2048 tokens
#define SCALING_F 2.0f        // 32/16
#define EPS_F 1e-5f

// ---------------- scratch (device globals; no runtime alloc) ----------------
__device__ float g_h   [BSN*DD];
__device__ float g_tmp [BSN*RR];
__device__ float g_xq  [BSN*HH*HDD];
__device__ float g_xk  [BSN*KVHH*HDD];
__device__ float g_xv  [BSN*KVHH*HDD];
__device__ float g_sc  [(size_t)BB*HH*SS*SS];      // 128 MB scores
__device__ float g_o   [BSN*HH*HDD];
__device__ float g_x2  [BSN*DD];
__device__ float g_sn  [BSN*DD];
__device__ float g_cw1 [(size_t)BSN*DFF];
__device__ float g_cw3 [(size_t)BSN*DFF];
__device__ float g_srw [(size_t)BSN*DFF];
__device__ float g_srs [(size_t)BSN*2*DFF];        // per-slot sr
__device__ float g_hs  [BSN*DD];
__device__ float g_logits[BSN*EE];
__device__ float g_mid1[BSN*EE*RR];
__device__ float g_mid3[BSN*EE*RR];
__device__ float g_mid2[BSN*2*RR];
__device__ float g_wsl [BSN*2];
__device__ int   g_sel [BSN*2];
__device__ int   g_cnt [EE];
__device__ int   g_list[EE*BSN];

// ---------------- small utility kernels ----------------
__global__ void copy_f4(const float4* __restrict__ src, float4* __restrict__ dst, int n) {
    int i = blockIdx.x * blockDim.x + threadIdx.x;
    if (i < n) dst[i] = src[i];
}

__global__ void zero_cnt_kernel() {
    if (threadIdx.x < EE) g_cnt[threadIdx.x] = 0;
}

// rmsnorm: one block per token row
__global__ __launch_bounds__(256) void rmsnorm_kernel(const float* __restrict__ x,
                                                      const float* __restrict__ w,
                                                      float* __restrict__ y) {
    int row = blockIdx.x;
    const float* xr = x + (size_t)row * DD;
    float* yr = y + (size_t)row * DD;
    float ss = 0.f;
    for (int i = threadIdx.x; i < DD; i += 256) { float v = xr[i]; ss += v * v; }
    __shared__ float red[256];
    red[threadIdx.x] = ss; __syncthreads();
    for (int s = 128; s > 0; s >>= 1) {
        if (threadIdx.x < s) red[threadIdx.x] += red[threadIdx.x + s];
        __syncthreads();
    }
    float scale = rsqrtf(red[0] / (float)DD + EPS_F);
    for (int i = threadIdx.x; i < DD; i += 256) yr[i] = xr[i] * scale * w[i];
}

// rope in place; nh heads per token; pair (d, d+64)
__global__ void rope_kernel(float* __restrict__ X, const float* __restrict__ cosb,
                            const float* __restrict__ sinb, int nh, int total) {
    int i = blockIdx.x * blockDim.x + threadIdx.x;
    if (i >= total) return;
    int d = i & 63;
    int rest = i >> 6;
    int hh = rest % nh;
    int bs = rest / nh;
    int s = bs & (SS - 1);
    size_t base = ((size_t)bs * nh + hh) * HDD;
    float x1 = X[base + d];
    float x2 = X[base + d + 64];
    float c1 = cosb[s * HDD + d];
    float c2 = cosb[s * HDD + d + 64];
    float s1 = sinb[s * HDD + d];
    float s2 = sinb[s * HDD + d + 64];
    X[base + d]      = x1 * c1 - x2 * s1;
    X[base + d + 64] = x2 * c2 + x1 * s2;
}

// ---------------- main 128x128x8 SGEMM ----------------
// C[M,N] = (accum ? C : 0) + alpha * A[M,K] @ B[K,N], row-major, dims multiples of tile
__global__ __launch_bounds__(256) void sgemm128(const float* __restrict__ A,
                                                const float* __restrict__ B,
                                                float* __restrict__ C,
                                                int K, int lda, int ldb, int ldc,
                                                float alpha, int accum) {
    __shared__ float As[8][128];
    __shared__ float Bs[8][128];
    int tid = threadIdx.x;
    int brow = blockIdx.y * 128;
    int bcol = blockIdx.x * 128;
    int tr = (tid / 16) * 8;
    int tc = (tid % 16) * 8;
    int arow = tid >> 1;
    int acol = (tid & 1) * 4;
    int brl = tid >> 5;
    int bcl = (tid & 31) * 4;
    const float* Ap = A + (size_t)(brow + arow) * lda + acol;
    const float* Bp = B + (size_t)brl * ldb + bcol + bcl;
    float acc[8][8];
#pragma unroll
    for (int i = 0; i < 8; i++)
#pragma unroll
        for (int j = 0; j < 8; j++) acc[i][j] = 0.f;

    for (int k0 = 0; k0 < K; k0 += 8) {
        float4 av = *(const float4*)(Ap + k0);
        float4 bv = *(const float4*)(Bp + (size_t)k0 * ldb);
        As[acol + 0][arow] = av.x;
        As[acol + 1][arow] = av.y;
        As[acol + 2][arow] = av.z;
        As[acol + 3][arow] = av.w;
        *(float4*)&Bs[brl][bcl] = bv;
        __syncthreads();
#pragma unroll
        for (int kk = 0; kk < 8; kk++) {
            float a0[8], b0[8];
            *(float4*)&a0[0] = *(const float4*)&As[kk][tr];
            *(float4*)&a0[4] = *(const float4*)&As[kk][tr + 4];
            *(float4*)&b0[0] = *(const float4*)&Bs[kk][tc];
            *(float4*)&b0[4] = *(const float4*)&Bs[kk][tc + 4];
#pragma unroll
            for (int i = 0; i < 8; i++)
#pragma unroll
                for (int j = 0; j < 8; j++) acc[i][j] += a0[i] * b0[j];
        }
        __syncthreads();
    }
#pragma unroll
    for (int i = 0; i < 8; i++) {
        float* Cr = C + (size_t)(brow + tr + i) * ldc + bcol + tc;
#pragma unroll
        for (int j4 = 0; j4 < 8; j4 += 4) {
            float4 cv;
            cv.x = alpha * acc[i][j4 + 0];
            cv.y = alpha * acc[i][j4 + 1];
            cv.z = alpha * acc[i][j4 + 2];
            cv.w = alpha * acc[i][j4 + 3];
            if (accum) {
                float4 old = *(const float4*)(Cr + j4);
                cv.x += old.x; cv.y += old.y; cv.z += old.z; cv.w += old.w;
            }
            *(float4*)(Cr + j4) = cv;
        }
    }
}

// ---------------- skinny GEMM (N = 8 or 16) ----------------
// C[row, cOff*batch + col] = A[row,:] @ Bbase[batch][:,col]
template <int NC>
__global__ __launch_bounds__(128) void skinny_gemm(const float* __restrict__ A,
                                                   const float* __restrict__ Bbase,
                                                   float* __restrict__ C,
                                                   int K, int lda, int ldb, int ldc,
                                                   long bstride, int cOff) {
    int row = blockIdx.x;
    int e = blockIdx.y;
    const float* Bp = Bbase + (size_t)e * bstride;
    const float* Ar = A + (size_t)row * lda;
    int tid = threadIdx.x;
    int col = tid % NC;
    int ksub = tid / NC;
    const int KL = 128 / NC;
    float acc = 0.f;
    for (int k = ksub; k < K; k += KL) acc += Ar[k] * Bp[(size_t)k * ldb + col];
    __shared__ float red[128];
    red[tid] = acc; __syncthreads();
    for (int s = KL / 2; s > 0; s >>= 1) {
        if (ksub < s) red[tid] += red[tid + s * NC];
        __syncthreads();
    }
    if (ksub == 0) C[(size_t)row * ldc + (size_t)e * cOff + col] = red[tid];
}

// ---------------- attention ----------------
__global__ __launch_bounds__(256) void attn_scores(const float* __restrict__ xq,
                                                   const float* __restrict__ xk) {
    int bh = blockIdx.z;
    int b = bh / HH, h = bh % HH, kvh = h >> 1;
    int q0 = blockIdx.y * 64, kc0 = blockIdx.x * 64;
    __shared__ float qs[32][64];
    __shared__ float ks[32][64];
    int tid = threadIdx.x;
    int tr = (tid / 16) * 4, tc = (tid % 16) * 4;
    const float* qb = xq + ((size_t)(b * SS + q0) * HH + h) * HDD;
    const float* kb = xk + ((size_t)(b * SS + kc0) * KVHH + kvh) * HDD;
    float acc[4][4];
#pragma unroll
    for (int i = 0; i < 4; i++)
#pragma unroll
        for (int j = 0; j < 4; j++) acc[i][j] = 0.f;

    for (int kk0 = 0; kk0 < HDD; kk0 += 32) {
#pragma unroll
        for (int l = 0; l < 2; l++) {
            int slot = tid + l * 256;
            int r = slot >> 3;
            int c4 = (slot & 7) * 4;
            float4 v = *(const float4*)(qb + (size_t)r * (HH * HDD) + kk0 + c4);
            qs[c4 + 0][r] = v.x; qs[c4 + 1][r] = v.y; qs[c4 + 2][r] = v.z; qs[c4 + 3][r] = v.w;
            float4 w = *(const float4*)(kb + (size_t)r * (KVHH * HDD) + kk0 + c4);
            ks[c4 + 0][r] = w.x; ks[c4 + 1][r] = w.y; ks[c4 + 2][r] = w.z; ks[c4 + 3][r] = w.w;
        }
        __syncthreads();
#pragma unroll
        for (int kk = 0; kk < 32; kk++) {
            float a0[4], b0[4];
            *(float4*)a0 = *(const float4*)&qs[kk][tr];
            *(float4*)b0 = *(const float4*)&ks[kk][tc];
#pragma unroll
            for (int i = 0; i < 4; i++)
#pragma unroll
                for (int j = 0; j < 4; j++) acc[i][j] += a0[i] * b0[j];
        }
        __syncthreads();
    }
    const float scale = 0.08838834764831845f; // 1/sqrt(128)
#pragma unroll
    for (int i = 0; i < 4; i++) {
        int q = q0 + tr + i;
#pragma unroll
        for (int j = 0; j < 4; j++) {
            int k = kc0 + tc + j;
            float v = acc[i][j] * scale + (k > q ? -1000000000.0f : 0.0f);
            g_sc[((size_t)bh * SS + q) * SS + k] = v;
        }
    }
}

__global__ __launch_bounds__(256) void softmax_rows() {
    size_t row = blockIdx.x;
    float* p = g_sc + row * (size_t)SS;
    int tid = threadIdx.x;
    float mx = -3.4e38f;
    float v[4];
#pragma unroll
    for (int l = 0; l < 4; l++) { v[l] = p[tid + l * 256]; mx = fmaxf(mx, v[l]); }
    __shared__ float red[256];
    red[tid] = mx; __syncthreads();
    for (int s = 128; s > 0; s >>= 1) { if (tid < s) red[tid] = fmaxf(red[tid], red[tid + s]); __syncthreads(); }
    mx = red[0]; __syncthreads();
    float sum = 0.f;
#pragma unroll
    for (int l = 0; l < 4; l++) { v[l] = expf(v[l] - mx); sum += v[l]; }
    red[tid] = sum; __syncthreads();
    for (int s = 128; s > 0; s >>= 1) { if (tid < s) red[tid] += red[tid + s]; __syncthreads(); }
    float inv = 1.f / red[0];
#pragma unroll
    for (int l = 0; l < 4; l++) p[tid + l * 256] = v[l] * inv;
}

__global__ __launch_bounds__(256) void attn_av(const float* __restrict__ xv,
                                               float* __restrict__ o) {
    int bh = blockIdx.z;
    int b = bh / HH, h = bh % HH, kvh = h >> 1;
    int q0 = blockIdx.y * 64, d0 = blockIdx.x * 64;
    __shared__ float as_[32][64];
    __shared__ float vs[32][64];
    int tid = threadIdx.x;
    int tr = (tid / 16) * 4, tc = (tid % 16) * 4;
    const float* ab = g_sc + ((size_t)bh * SS + q0) * SS;
    float acc[4][4];
#pragma unroll
    for (int i = 0; i < 4; i++)
#pragma unroll
        for (int j = 0; j < 4; j++) acc[i][j] = 0.f;

    for (int k0 = 0; k0 < SS; k0 += 32) {
#pragma unroll
        for (int l = 0; l < 2; l++) {
            int slot = tid + l * 256;
            // attn tile: 64 q rows x 32 k cols, store transposed
            int r = slot >> 3;
            int c4 = (slot & 7) * 4;
            float4 v = *(const float4*)(ab + (size_t)r * SS + k0 + c4);
            as_[c4 + 0][r] = v.x; as_[c4 + 1][r] = v.y; as_[c4 + 2][r] = v.z; as_[c4 + 3][r] = v.w;
            // v tile: 32 k rows x 64 d cols, natural
            int kr = slot >> 4;
            int dc4 = (slot & 15) * 4;
            float4 w = *(const float4*)(xv + ((size_t)(b * SS + k0 + kr) * KVHH + kvh) * HDD + d0 + dc4);
            *(float4*)&vs[kr][dc4] = w;
        }
        __syncthreads();
#pragma unroll
        for (int kk = 0; kk < 32; kk++) {
            float a0[4], b0[4];
            *(float4*)a0 = *(const float4*)&as_[kk][tr];
            *(float4*)b0 = *(const float4*)&vs[kk][tc];
#pragma unroll
            for (int i = 0; i < 4; i++)
#pragma unroll
                for (int j = 0; j < 4; j++) acc[i][j] += a0[i] * b0[j];
        }
        __syncthreads();
    }
#pragma unroll
    for (int i = 0; i < 4; i++) {
        int q = q0 + tr + i;
#pragma unroll
        for (int j = 0; j < 4; j++)
            o[((size_t)(b * SS + q) * HH + h) * HDD + d0 + tc + j] = acc[i][j];
    }
}

// ---------------- MoE routing ----------------
__global__ void gate_topk() {
    int t = blockIdx.x * blockDim.x + threadIdx.x;
    if (t >= BSN) return;
    float l[EE];
    float mx = -3.4e38f;
#pragma unroll
    for (int e = 0; e < EE; e++) { l[e] = g_logits[t * EE + e]; mx = fmaxf(mx, l[e]); }
    float sum = 0.f;
#pragma unroll
    for (int e = 0; e < EE; e++) { l[e] = expf(l[e] - mx); sum += l[e]; }
#pragma unroll
    for (int e = 0; e < EE; e++) l[e] /= sum;
    int i0 = 0;
#pragma unroll
    for (int e = 1; e < EE; e++) if (l[e] > l[i0]) i0 = e;
    int i1 = (i0 == 0) ? 1 : 0;
#pragma unroll
    for (int e = 0; e < EE; e++) if (e != i0 && l[e] > l[i1]) i1 = e;
    float s2 = l[i0] + l[i1];
    g_wsl[t * 2 + 0] = l[i0] / s2;
    g_wsl[t * 2 + 1] = l[i1] / s2;
    g_sel[t * 2 + 0] = i0;
    g_sel[t * 2 + 1] = i1;
    int p0 = atomicAdd(&g_cnt[i0], 1);
    g_list[i0 * BSN + p0] = t * 2;
    int p1 = atomicAdd(&g_cnt[i1], 1);
    g_list[i1 * BSN + p1] = t * 2 + 1;
}

// per-expert fused SwiGLU + rank-16 LoRA: writes sr per (token, slot)
__global__ __launch_bounds__(256) void expert_kernel(const float* __restrict__ b1,
                                                     const float* __restrict__ b3) {
    int e = blockIdx.y;
    int j0 = blockIdx.x * 256;
    __shared__ float b1s[RR][256];
    __shared__ float b3s[RR][256];
    int tid = threadIdx.x;
#pragma unroll
    for (int r = 0; r < RR; r++) {
        b1s[r][tid] = b1[((size_t)e * RR + r) * DFF + j0 + tid];
        b3s[r][tid] = b3[((size_t)e * RR + r) * DFF + j0 + tid];
    }
    __syncthreads();
    int n = g_cnt[e];
    for (int i = 0; i < n; i++) {
        int ent = g_list[e * BSN + i];
        int t = ent >> 1, slot = ent & 1;
        float x1 = g_cw1[(size_t)t * DFF + j0 + tid];
        float x3 = g_cw3[(size_t)t * DFF + j0 + tid];
        const float* m1 = &g_mid1[(size_t)t * EE * RR + e * RR];
        const float* m3 = &g_mid3[(size_t)t * EE * RR + e * RR];
#pragma unroll
        for (int r = 0; r < RR; r++) {
            x1 += SCALING_F * m1[r] * b1s[r][tid];
            x3 += SCALING_F * m3[r] * b3s[r][tid];
        }
        float sr = x1 / (1.f + expf(-x1)) * x3;
        g_srs[((size_t)t * 2 + slot) * DFF + j0 + tid] = sr;
    }
}

__global__ void combine_srw(int total) {
    int i = blockIdx.x * blockDim.x + threadIdx.x;
    if (i >= total) return;
    int t = i / DFF;
    int j = i % DFF;
    g_srw[(size_t)i] = g_wsl[t * 2 + 0] * g_srs[((size_t)t * 2 + 0) * DFF + j]
                     + g_wsl[t * 2 + 1] * g_srs[((size_t)t * 2 + 1) * DFF + j];
}

// mid2[t,slot,r] = sr_slot[t,slot,:] @ a2[sel][:,r]
__global__ __launch_bounds__(256) void mid2_kernel(const float* __restrict__ a2) {
    int ts = blockIdx.x;
    int t = ts >> 1, slot = ts & 1;
    int e = g_sel[t * 2 + slot];
    const float* sr = g_srs + (size_t)ts * DFF;
    const float* A2 = a2 + (size_t)e * DFF * RR;
    int tid = threadIdx.x;
    int r = tid % RR;
    int jo = tid / RR; // 16 j lanes
    float acc = 0.f;
    for (int j = jo; j < DFF; j += 16) acc += sr[j] * A2[(size_t)j * RR + r];
    __shared__ float red[256];
    red[tid] = acc; __syncthreads();
    for (int s = 8; s > 0; s >>= 1) {
        if (jo < s) red[tid] += red[tid + s * RR];
        __syncthreads();
    }
    if (jo == 0) g_mid2[(size_t)ts * RR + r] = red[tid];
}

// out = x2 + hs + sum_slot wsl*SCALING* mid2 @ b2[sel]
__global__ __launch_bounds__(256) void final_epilogue(const float* __restrict__ b2,
                                                      float* __restrict__ out) {
    int t = blockIdx.x;
    __shared__ float m2s[2][RR];
    __shared__ float ws[2];
    __shared__ int es[2];
    int tid = threadIdx.x;
    if (tid < 32) {
        int slot = tid / RR, r = tid % RR;
        m2s[slot][r] = g_mid2[(size_t)(t * 2 + slot) * RR + r];
    }
    if (tid < 2) { ws[tid] = g_wsl[t * 2 + tid]; es[tid] = g_sel[t * 2 + tid]; }
    __syncthreads();
    for (int d = tid; d < DD; d += 256) {
        float acc = g_x2[(size_t)t * DD + d] + g_hs[(size_t)t * DD + d];
#pragma unroll
        for (int slot = 0; slot < 2; slot++) {
            const float* B2 = b2 + (size_t)es[slot] * RR * DD;
            float c = 0.f;
#pragma unroll
            for (int r = 0; r < RR; r++) c += m2s[slot][r] * B2[(size_t)r * DD + d];
            acc += ws[slot] * SCALING_F * c;
        }
        out[(size_t)t * DD + d] = acc;
    }
}

// ---------------- launch ----------------
extern "C" void kernel_launch(void* const* d_in, const int* in_sizes, int n_in,
                              void* d_out, int out_size) {
    const float* data = (const float*)d_in[0];
    const float* cosb = (const float*)d_in[2];
    const float* sinb = (const float*)d_in[3];
    const float* anw  = (const float*)d_in[4];
    const float* fnw  = (const float*)d_in[5];
    const float* wq   = (const float*)d_in[6];
    const float* wk   = (const float*)d_in[7];
    const float* wv   = (const float*)d_in[8];
    const float* wo   = (const float*)d_in[9];
    const float* qa   = (const float*)d_in[10];
    const float* qb   = (const float*)d_in[11];
    const float* ka   = (const float*)d_in[12];
    const float* kb   = (const float*)d_in[13];
    const float* va   = (const float*)d_in[14];
    const float* vb   = (const float*)d_in[15];
    const float* oa   = (const float*)d_in[16];
    const float* ob   = (const float*)d_in[17];
    const float* gw   = (const float*)d_in[18];
    const float* w1   = (const float*)d_in[19];
    const float* w2   = (const float*)d_in[20];
    const float* w3   = (const float*)d_in[21];
    const float* a1   = (const float*)d_in[22];
    const float* b1   = (const float*)d_in[23];
    const float* a3   = (const float*)d_in[24];
    const float* b3   = (const float*)d_in[25];
    const float* a2   = (const float*)d_in[26];
    const float* b2   = (const float*)d_in[27];
    float* out = (float*)d_out;

    float *p_h, *p_tmp, *p_xq, *p_xk, *p_xv, *p_o, *p_x2, *p_sn;
    float *p_cw1, *p_cw3, *p_srw, *p_hs, *p_logits, *p_mid1, *p_mid3;
    cudaGetSymbolAddress((void**)&p_h,   g_h);
    cudaGetSymbolAddress((void**)&p_tmp, g_tmp);
    cudaGetSymbolAddress((void**)&p_xq,  g_xq);
    cudaGetSymbolAddress((void**)&p_xk,  g_xk);
    cudaGetSymbolAddress((void**)&p_xv,  g_xv);
    cudaGetSymbolAddress((void**)&p_o,   g_o);
    cudaGetSymbolAddress((void**)&p_x2,  g_x2);
    cudaGetSymbolAddress((void**)&p_sn,  g_sn);
    cudaGetSymbolAddress((void**)&p_cw1, g_cw1);
    cudaGetSymbolAddress((void**)&p_cw3, g_cw3);
    cudaGetSymbolAddress((void**)&p_srw, g_srw);
    cudaGetSymbolAddress((void**)&p_hs,  g_hs);
    cudaGetSymbolAddress((void**)&p_logits, g_logits);
    cudaGetSymbolAddress((void**)&p_mid1, g_mid1);
    cudaGetSymbolAddress((void**)&p_mid3, g_mid3);

    // 1. rmsnorm 1
    rmsnorm_kernel<<<BSN, 256>>>(data, anw, p_h);

    // 2. QKV projections + LoRA
    sgemm128<<<dim3(DD/128, BSN/128), 256>>>(p_h, wq, p_xq, DD, DD, DD, DD, 1.f, 0);
    skinny_gemm<16><<<dim3(BSN,1), 128>>>(p_h, qa, p_tmp, DD, DD, RR, RR, 0, 0);
    sgemm128<<<dim3(DD/128, BSN/128), 256>>>(p_tmp, qb, p_xq, RR, RR, DD, DD, SCALING_F, 1);

    sgemm128<<<dim3((KVHH*HDD)/128, BSN/128), 256>>>(p_h, wk, p_xk, DD, DD, KVHH*HDD, KVHH*HDD, 1.f, 0);
    skinny_gemm<16><<<dim3(BSN,1), 128>>>(p_h, ka, p_tmp, DD, DD, RR, RR, 0, 0);
    sgemm128<<<dim3((KVHH*HDD)/128, BSN/128), 256>>>(p_tmp, kb, p_xk, RR, RR, KVHH*HDD, KVHH*HDD, SCALING_F, 1);

    sgemm128<<<dim3((KVHH*HDD)/128, BSN/128), 256>>>(p_h, wv, p_xv, DD, DD, KVHH*HDD, KVHH*HDD, 1.f, 0);
    skinny_gemm<16><<<dim3(BSN,1), 128>>>(p_h, va, p_tmp, DD, DD, RR, RR, 0, 0);
    sgemm128<<<dim3((KVHH*HDD)/128, BSN/128), 256>>>(p_tmp, vb, p_xv, RR, RR, KVHH*HDD, KVHH*HDD, SCALING_F, 1);

    // 3. RoPE
    rope_kernel<<<(BSN*HH*64 + 255)/256, 256>>>(p_xq, cosb, sinb, HH, BSN*HH*64);
    rope_kernel<<<(BSN*KVHH*64 + 255)/256, 256>>>(p_xk, cosb, sinb, KVHH, BSN*KVHH*64);

    // 4. attention
    attn_scores<<<dim3(SS/64, SS/64, BB*HH), 256>>>(p_xq, p_xk);
    softmax_rows<<<BB*HH*SS, 256>>>();
    attn_av<<<dim3(HDD/64, SS/64, BB*HH), 256>>>(p_xv, p_o);

    // 5. output projection + LoRA + residual
    copy_f4<<<(BSN*DD/4 + 255)/256, 256>>>((const float4*)data, (float4*)p_x2, BSN*DD/4);
    sgemm128<<<dim3(DD/128, BSN/128), 256>>>(p_o, wo, p_x2, HH*HDD, HH*HDD, DD, DD, 1.f, 1);
    skinny_gemm<16><<<dim3(BSN,1), 128>>>(p_o, oa, p_tmp, HH*HDD, HH*HDD, RR, RR, 0, 0);
    sgemm128<<<dim3(DD/128, BSN/128), 256>>>(p_tmp, ob, p_x2, RR, RR, DD, DD, SCALING_F, 1);

    // 6. rmsnorm 2
    rmsnorm_kernel<<<BSN, 256>>>(p_x2, fnw, p_sn);

    // 7. shared FFN GEMMs
    sgemm128<<<dim3(DFF/128, BSN/128), 256>>>(p_sn, w1, p_cw1, DD, DD, DFF, DFF, 1.f, 0);
    sgemm128<<<dim3(DFF/128, BSN/128), 256>>>(p_sn, w3, p_cw3, DD, DD, DFF, DFF, 1.f, 0);

    // 8. gating
    skinny_gemm<8><<<dim3(BSN,1), 128>>>(p_sn, gw, p_logits, DD, DD, EE, EE, 0, 0);
    zero_cnt_kernel<<<1, 32>>>();
    gate_topk<<<(BSN + 255)/256, 256>>>();

    // 9. per-expert LoRA mids (all experts, cheap)
    skinny_gemm<16><<<dim3(BSN, EE), 128>>>(p_sn, a1, p_mid1, DD, DD, RR, EE*RR, (long)DD*RR, RR);
    skinny_gemm<16><<<dim3(BSN, EE), 128>>>(p_sn, a3, p_mid3, DD, DD, RR, EE*RR, (long)DD*RR, RR);

    // 10. fused expert SwiGLU (selected tokens only)
    expert_kernel<<<dim3(DFF/256, EE), 256>>>(b1, b3);

    // 11. weighted combine + shared w2 GEMM
    combine_srw<<<(BSN*DFF + 255)/256, 256>>>(BSN*DFF);
    sgemm128<<<dim3(DD/128, BSN/128), 256>>>(p_srw, w2, p_hs, DFF, DFF, DD, DD, 1.f, 0);

    // 12. lora2 mids + final epilogue
    mid2_kernel<<<BSN*2, 256>>>(a2);
    final_epilogue<<<BSN, 256>>>(b2, out);
}

// round 5
// speedup vs baseline: 2.0113x; 1.9955x over previous
#include <cuda_runtime.h>
#include <math.h>
#include <stdint.h>

// ---------------- problem constants ----------------
#define BB   2
#define SS   1024
#define DD   2048
#define HH   16
#define KVHH 8
#define HDD  128
#define DFF  8192
#define EE   8
#define RR   16
#define BSN  (BB*SS)          // 2048 tokens
#define SCALING_F 2.0f        // 32/16
#define EPS_F 1e-5f

// ---------------- scratch (device globals; no runtime alloc) ----------------
__device__ float g_h   [BSN*DD];
__device__ float g_tmp [BSN*RR];
__device__ float g_xq  [BSN*HH*HDD];
__device__ float g_xk  [BSN*KVHH*HDD];
__device__ float g_xv  [BSN*KVHH*HDD];
__device__ float g_sc  [(size_t)BB*HH*SS*SS];      // 128 MB scores
__device__ float g_o   [BSN*HH*HDD];
__device__ float g_x2  [BSN*DD];
__device__ float g_sn  [BSN*DD];
__device__ float g_cw1 [(size_t)BSN*DFF];
__device__ float g_cw3 [(size_t)BSN*DFF];
__device__ float g_srw [(size_t)BSN*DFF];
__device__ float g_srs [(size_t)BSN*2*DFF];        // per-slot sr
__device__ float g_hs  [BSN*DD];
__device__ float g_logits[BSN*EE];
__device__ float g_mid1[BSN*EE*RR];
__device__ float g_mid3[BSN*EE*RR];
__device__ float g_mid2[BSN*2*RR];
__device__ float g_wsl [BSN*2];
__device__ int   g_sel [BSN*2];
__device__ int   g_cnt [EE];
__device__ int   g_list[EE*BSN];

// ---------------- helpers ----------------
__device__ __forceinline__ uint32_t to_tf32(float f) {
    uint32_t r;
    asm("cvt.rna.tf32.f32 %0, %1;" : "=r"(r) : "f"(f));
    return r;
}

__device__ __forceinline__ void mma_tf32_16x8x8(float c[4], uint32_t a0, uint32_t a1,
                                                uint32_t a2, uint32_t a3,
                                                uint32_t b0, uint32_t b1) {
    asm volatile(
        "mma.sync.aligned.m16n8k8.row.col.f32.tf32.tf32.f32 "
        "{%0,%1,%2,%3}, {%4,%5,%6,%7}, {%8,%9}, {%0,%1,%2,%3};"
        : "+f"(c[0]), "+f"(c[1]), "+f"(c[2]), "+f"(c[3])
        : "r"(a0), "r"(a1), "r"(a2), "r"(a3), "r"(b0), "r"(b1));
}

// ================= tf32 mma.sync GEMM =================
// C[M,N] = A[M,K] @ B[K,N] (+C if accum). M,N multiples of 128, K multiple of 32.
// Block 256 threads (8 warps), tile 128x128x32, warp tile 64x32.
#define TS_STRIDE 36

__global__ __launch_bounds__(256) void tgemm_mma(const float* __restrict__ A,
                                                 const float* __restrict__ B,
                                                 float* __restrict__ C,
                                                 int K, int lda, int ldb, int ldc,
                                                 int accum) {
    __shared__ float As[128 * TS_STRIDE];
    __shared__ float Bs[128 * TS_STRIDE];

    const int tid  = threadIdx.x;
    const int wid  = tid >> 5;
    const int lane = tid & 31;
    const int brow = blockIdx.y * 128;
    const int bcol = blockIdx.x * 128;

    const int wm = (wid & 1) * 64;     // warp m offset (0/64)
    const int wn = (wid >> 1) * 32;    // warp n offset (0/32/64/96)

    // A loader: row = (tid>>3)+i*32, kc = tid&7 -> float4 at [row][4*kc]
    const int a_row = tid >> 3;
    const int a_kc  = tid & 7;
    // B loader: n = tid&127, kq0 = tid>>7 (handles kq0, kq0+2, +4, +6)
    const int b_n   = tid & 127;
    const int b_kq0 = tid >> 7;

    float acc[4][4][4];
#pragma unroll
    for (int i = 0; i < 4; i++)
#pragma unroll
        for (int j = 0; j < 4; j++)
#pragma unroll
            for (int q = 0; q < 4; q++) acc[i][j][q] = 0.f;

    float4 aPre[4];
    float  bPre[4][4];

    // prefetch tile 0
#pragma unroll
    for (int i = 0; i < 4; i++)
        aPre[i] = *(const float4*)(A + (size_t)(brow + a_row + i * 32) * lda + a_kc * 4);
#pragma unroll
    for (int i = 0; i < 4; i++) {
        int kq = b_kq0 + i * 2;
#pragma unroll
        for (int j = 0; j < 4; j++)
            bPre[i][j] = B[(size_t)(kq * 4 + j) * ldb + bcol + b_n];
    }

    const int T = K >> 5;
    for (int t = 0; t < T; t++) {
        // store prefetched tile into smem
#pragma unroll
        for (int i = 0; i < 4; i++)
            *(float4*)&As[(a_row + i * 32) * TS_STRIDE + a_kc * 4] = aPre[i];
#pragma unroll
        for (int i = 0; i < 4; i++) {
            int kq = b_kq0 + i * 2;
            float4 v = make_float4(bPre[i][0], bPre[i][1], bPre[i][2], bPre[i][3]);
            *(float4*)&Bs[b_n * TS_STRIDE + kq * 4] = v;
        }
        __syncthreads();

        // prefetch next tile
        if (t + 1 < T) {
            int k0 = (t + 1) << 5;
#pragma unroll
            for (int i = 0; i < 4; i++)
                aPre[i] = *(const float4*)(A + (size_t)(brow + a_row + i * 32) * lda + k0 + a_kc * 4);
#pragma unroll
            for (int i = 0; i < 4; i++) {
                int kq = b_kq0 + i * 2;
#pragma unroll
                for (int j = 0; j < 4; j++)
                    bPre[i][j] = B[(size_t)(k0 + kq * 4 + j) * ldb + bcol + b_n];
            }
        }

        // compute on current smem tile
        const int lr = lane >> 2;     // 0..7
        const int lc = lane & 3;      // 0..3
#pragma unroll
        for (int ks = 0; ks < 4; ks++) {
            const int k = ks * 8;
            uint32_t af[4][4];
            uint32_t bf[4][2];
#pragma unroll
            for (int mi = 0; mi < 4; mi++) {
                int m = wm + mi * 16 + lr;
                af[mi][0] = to_tf32(As[m * TS_STRIDE + k + lc]);
                af[mi][1] = to_tf32(As[(m + 8) * TS_STRIDE + k + lc]);
                af[mi][2] = to_tf32(As[m * TS_STRIDE + k + lc + 4]);
                af[mi][3] = to_tf32(As[(m + 8) * TS_STRIDE + k + lc + 4]);
            }
#pragma unroll
            for (int ni = 0; ni < 4; ni++) {
                int n = wn + ni * 8 + lr;
                bf[ni][0] = to_tf32(Bs[n * TS_STRIDE + k + lc]);
                bf[ni][1] = to_tf32(Bs[n * TS_STRIDE + k + lc + 4]);
            }
#pragma unroll
            for (int mi = 0; mi < 4; mi++)
#pragma unroll
                for (int ni = 0; ni < 4; ni++)
                    mma_tf32_16x8x8(acc[mi][ni], af[mi][0], af[mi][1], af[mi][2], af[mi][3],
                                    bf[ni][0], bf[ni][1]);
        }
        __syncthreads();
    }

    // epilogue
    const int lr = lane >> 2;
    const int lc = lane & 3;
#pragma unroll
    for (int mi = 0; mi < 4; mi++) {
#pragma unroll
        for (int ni = 0; ni < 4; ni++) {
            int row0 = brow + wm + mi * 16 + lr;
            int col0 = bcol + wn + ni * 8 + 2 * lc;
            float* p0 = C + (size_t)row0 * ldc + col0;
            float* p1 = C + (size_t)(row0 + 8) * ldc + col0;
            float2 v0 = make_float2(acc[mi][ni][0], acc[mi][ni][1]);
            float2 v1 = make_float2(acc[mi][ni][2], acc[mi][ni][3]);
            if (accum) {
                float2 o0 = *(const float2*)p0;
                float2 o1 = *(const float2*)p1;
                v0.x += o0.x; v0.y += o0.y;
                v1.x += o1.x; v1.y += o1.y;
            }
            *(float2*)p0 = v0;
            *(float2*)p1 = v1;
        }
    }
}

// ---------------- small utility kernels ----------------
__global__ void copy_f4(const float4* __restrict__ src, float4* __restrict__ dst, int n) {
    int i = blockIdx.x * blockDim.x + threadIdx.x;
    if (i < n) dst[i] = src[i];
}

__global__ void zero_cnt_kernel() {
    if (threadIdx.x < EE) g_cnt[threadIdx.x] = 0;
}

__global__ __launch_bounds__(256) void rmsnorm_kernel(const float* __restrict__ x,
                                                      const float* __restrict__ w,
                                                      float* __restrict__ y) {
    int row = blockIdx.x;
    const float* xr = x + (size_t)row * DD;
    float* yr = y + (size_t)row * DD;
    float ss = 0.f;
    for (int i = threadIdx.x; i < DD; i += 256) { float v = xr[i]; ss += v * v; }
    __shared__ float red[256];
    red[threadIdx.x] = ss; __syncthreads();
    for (int s = 128; s > 0; s >>= 1) {
        if (threadIdx.x < s) red[threadIdx.x] += red[threadIdx.x + s];
        __syncthreads();
    }
    float scale = rsqrtf(red[0] / (float)DD + EPS_F);
    for (int i = threadIdx.x; i < DD; i += 256) yr[i] = xr[i] * scale * w[i];
}

__global__ void rope_kernel(float* __restrict__ X, const float* __restrict__ cosb,
                            const float* __restrict__ sinb, int nh, int total) {
    int i = blockIdx.x * blockDim.x + threadIdx.x;
    if (i >= total) return;
    int d = i & 63;
    int rest = i >> 6;
    int hh = rest % nh;
    int bs = rest / nh;
    int s = bs & (SS - 1);
    size_t base = ((size_t)bs * nh + hh) * HDD;
    float x1 = X[base + d];
    float x2 = X[base + d + 64];
    float c1 = cosb[s * HDD + d];
    float c2 = cosb[s * HDD + d + 64];
    float s1 = sinb[s * HDD + d];
    float s2 = sinb[s * HDD + d + 64];
    X[base + d]      = x1 * c1 - x2 * s1;
    X[base + d + 64] = x2 * c2 + x1 * s2;
}

// ---------------- fp32 SIMT GEMM (kept for K=16 LoRA applies) ----------------
__global__ __launch_bounds__(256) void sgemm128(const float* __restrict__ A,
                                                const float* __restrict__ B,
                                                float* __restrict__ C,
                                                int K, int lda, int ldb, int ldc,
                                                float alpha, int accum) {
    __shared__ float As[8][128];
    __shared__ float Bs[8][128];
    int tid = threadIdx.x;
    int brow = blockIdx.y * 128;
    int bcol = blockIdx.x * 128;
    int tr = (tid / 16) * 8;
    int tc = (tid % 16) * 8;
    int arow = tid >> 1;
    int acol = (tid & 1) * 4;
    int brl = tid >> 5;
    int bcl = (tid & 31) * 4;
    const float* Ap = A + (size_t)(brow + arow) * lda + acol;
    const float* Bp = B + (size_t)brl * ldb + bcol + bcl;
    float acc[8][8];
#pragma unroll
    for (int i = 0; i < 8; i++)
#pragma unroll
        for (int j = 0; j < 8; j++) acc[i][j] = 0.f;

    for (int k0 = 0; k0 < K; k0 += 8) {
        float4 av = *(const float4*)(Ap + k0);
        float4 bv = *(const float4*)(Bp + (size_t)k0 * ldb);
        As[acol + 0][arow] = av.x;
        As[acol + 1][arow] = av.y;
        As[acol + 2][arow] = av.z;
        As[acol + 3][arow] = av.w;
        *(float4*)&Bs[brl][bcl] = bv;
        __syncthreads();
#pragma unroll
        for (int kk = 0; kk < 8; kk++) {
            float a0[8], b0[8];
            *(float4*)&a0[0] = *(const float4*)&As[kk][tr];
            *(float4*)&a0[4] = *(const float4*)&As[kk][tr + 4];
            *(float4*)&b0[0] = *(const float4*)&Bs[kk][tc];
            *(float4*)&b0[4] = *(const float4*)&Bs[kk][tc + 4];
#pragma unroll
            for (int i = 0; i < 8; i++)
#pragma unroll
                for (int j = 0; j < 8; j++) acc[i][j] += a0[i] * b0[j];
        }
        __syncthreads();
    }
#pragma unroll
    for (int i = 0; i < 8; i++) {
        float* Cr = C + (size_t)(brow + tr + i) * ldc + bcol + tc;
#pragma unroll
        for (int j4 = 0; j4 < 8; j4 += 4) {
            float4 cv;
            cv.x = alpha * acc[i][j4 + 0];
            cv.y = alpha * acc[i][j4 + 1];
            cv.z = alpha * acc[i][j4 + 2];
            cv.w = alpha * acc[i][j4 + 3];
            if (accum) {
                float4 old = *(const float4*)(Cr + j4);
                cv.x += old.x; cv.y += old.y; cv.z += old.z; cv.w += old.w;
            }
            *(float4*)(Cr + j4) = cv;
        }
    }
}

// ---------------- skinny GEMM (N = 8 or 16) ----------------
template <int NC>
__global__ __launch_bounds__(128) void skinny_gemm(const float* __restrict__ A,
                                                   const float* __restrict__ Bbase,
                                                   float* __restrict__ C,
                                                   int K, int lda, int ldb, int ldc,
                                                   long bstride, int cOff) {
    int row = blockIdx.x;
    int e = blockIdx.y;
    const float* Bp = Bbase + (size_t)e * bstride;
    const float* Ar = A + (size_t)row * lda;
    int tid = threadIdx.x;
    int col = tid % NC;
    int ksub = tid / NC;
    const int KL = 128 / NC;
    float acc = 0.f;
    for (int k = ksub; k < K; k += KL) acc += Ar[k] * Bp[(size_t)k * ldb + col];
    __shared__ float red[128];
    red[tid] = acc; __syncthreads();
    for (int s = KL / 2; s > 0; s >>= 1) {
        if (ksub < s) red[tid] += red[tid + s * NC];
        __syncthreads();
    }
    if (ksub == 0) C[(size_t)row * ldc + (size_t)e * cOff + col] = red[tid];
}

// ---------------- attention ----------------
__global__ __launch_bounds__(256) void attn_scores(const float* __restrict__ xq,
                                                   const float* __restrict__ xk) {
    int bh = blockIdx.z;
    int b = bh / HH, h = bh % HH, kvh = h >> 1;
    int q0 = blockIdx.y * 64, kc0 = blockIdx.x * 64;
    __shared__ float qs[32][64];
    __shared__ float ks[32][64];
    int tid = threadIdx.x;
    int tr = (tid / 16) * 4, tc = (tid % 16) * 4;
    const float* qb = xq + ((size_t)(b * SS + q0) * HH + h) * HDD;
    const float* kb = xk + ((size_t)(b * SS + kc0) * KVHH + kvh) * HDD;
    float acc[4][4];
#pragma unroll
    for (int i = 0; i < 4; i++)
#pragma unroll
        for (int j = 0; j < 4; j++) acc[i][j] = 0.f;

    for (int kk0 = 0; kk0 < HDD; kk0 += 32) {
#pragma unroll
        for (int l = 0; l < 2; l++) {
            int slot = tid + l * 256;
            int r = slot >> 3;
            int c4 = (slot & 7) * 4;
            float4 v = *(const float4*)(qb + (size_t)r * (HH * HDD) + kk0 + c4);
            qs[c4 + 0][r] = v.x; qs[c4 + 1][r] = v.y; qs[c4 + 2][r] = v.z; qs[c4 + 3][r] = v.w;
            float4 w = *(const float4*)(kb + (size_t)r * (KVHH * HDD) + kk0 + c4);
            ks[c4 + 0][r] = w.x; ks[c4 + 1][r] = w.y; ks[c4 + 2][r] = w.z; ks[c4 + 3][r] = w.w;
        }
        __syncthreads();
#pragma unroll
        for (int kk = 0; kk < 32; kk++) {
            float a0[4], b0[4];
            *(float4*)a0 = *(const float4*)&qs[kk][tr];
            *(float4*)b0 = *(const float4*)&ks[kk][tc];
#pragma unroll
            for (int i = 0; i < 4; i++)
#pragma unroll
                for (int j = 0; j < 4; j++) acc[i][j] += a0[i] * b0[j];
        }
        __syncthreads();
    }
    const float scale = 0.08838834764831845f; // 1/sqrt(128)
#pragma unroll
    for (int i = 0; i < 4; i++) {
        int q = q0 + tr + i;
#pragma unroll
        for (int j = 0; j < 4; j++) {
            int k = kc0 + tc + j;
            float v = acc[i][j] * scale + (k > q ? -1000000000.0f : 0.0f);
            g_sc[((size_t)bh * SS + q) * SS + k] = v;
        }
    }
}

__global__ __launch_bounds__(256) void softmax_rows() {
    size_t row = blockIdx.x;
    float* p = g_sc + row * (size_t)SS;
    int tid = threadIdx.x;
    float mx = -3.4e38f;
    float v[4];
#pragma unroll
    for (int l = 0; l < 4; l++) { v[l] = p[tid + l * 256]; mx = fmaxf(mx, v[l]); }
    __shared__ float red[256];
    red[tid] = mx; __syncthreads();
    for (int s = 128; s > 0; s >>= 1) { if (tid < s) red[tid] = fmaxf(red[tid], red[tid + s]); __syncthreads(); }
    mx = red[0]; __syncthreads();
    float sum = 0.f;
#pragma unroll
    for (int l = 0; l < 4; l++) { v[l] = expf(v[l] - mx); sum += v[l]; }
    red[tid] = sum; __syncthreads();
    for (int s = 128; s > 0; s >>= 1) { if (tid < s) red[tid] += red[tid + s]; __syncthreads(); }
    float inv = 1.f / red[0];
#pragma unroll
    for (int l = 0; l < 4; l++) p[tid + l * 256] = v[l] * inv;
}

__global__ __launch_bounds__(256) void attn_av(const float* __restrict__ xv,
                                               float* __restrict__ o) {
    int bh = blockIdx.z;
    int b = bh / HH, h = bh % HH, kvh = h >> 1;
    int q0 = blockIdx.y * 64, d0 = blockIdx.x * 64;
    __shared__ float as_[32][64];
    __shared__ float vs[32][64];
    int tid = threadIdx.x;
    int tr = (tid / 16) * 4, tc = (tid % 16) * 4;
    const float* ab = g_sc + ((size_t)bh * SS + q0) * SS;
    float acc[4][4];
#pragma unroll
    for (int i = 0; i < 4; i++)
#pragma unroll
        for (int j = 0; j < 4; j++) acc[i][j] = 0.f;

    for (int k0 = 0; k0 < SS; k0 += 32) {
#pragma unroll
        for (int l = 0; l < 2; l++) {
            int slot = tid + l * 256;
            int r = slot >> 3;
            int c4 = (slot & 7) * 4;
            float4 v = *(const float4*)(ab + (size_t)r * SS + k0 + c4);
            as_[c4 + 0][r] = v.x; as_[c4 + 1][r] = v.y; as_[c4 + 2][r] = v.z; as_[c4 + 3][r] = v.w;
            int kr = slot >> 4;
            int dc4 = (slot & 15) * 4;
            float4 w = *(const float4*)(xv + ((size_t)(b * SS + k0 + kr) * KVHH + kvh) * HDD + d0 + dc4);
            *(float4*)&vs[kr][dc4] = w;
        }
        __syncthreads();
#pragma unroll
        for (int kk = 0; kk < 32; kk++) {
            float a0[4], b0[4];
            *(float4*)a0 = *(const float4*)&as_[kk][tr];
            *(float4*)b0 = *(const float4*)&vs[kk][tc];
#pragma unroll
            for (int i = 0; i < 4; i++)
#pragma unroll
                for (int j = 0; j < 4; j++) acc[i][j] += a0[i] * b0[j];
        }
        __syncthreads();
    }
#pragma unroll
    for (int i = 0; i < 4; i++) {
        int q = q0 + tr + i;
#pragma unroll
        for (int j = 0; j < 4; j++)
            o[((size_t)(b * SS + q) * HH + h) * HDD + d0 + tc + j] = acc[i][j];
    }
}

// ---------------- MoE routing ----------------
__global__ void gate_topk() {
    int t = blockIdx.x * blockDim.x + threadIdx.x;
    if (t >= BSN) return;
    float l[EE];
    float mx = -3.4e38f;
#pragma unroll
    for (int e = 0; e < EE; e++) { l[e] = g_logits[t * EE + e]; mx = fmaxf(mx, l[e]); }
    float sum = 0.f;
#pragma unroll
    for (int e = 0; e < EE; e++) { l[e] = expf(l[e] - mx); sum += l[e]; }
#pragma unroll
    for (int e = 0; e < EE; e++) l[e] /= sum;
    int i0 = 0;
#pragma unroll
    for (int e = 1; e < EE; e++) if (l[e] > l[i0]) i0 = e;
    int i1 = (i0 == 0) ? 1 : 0;
#pragma unroll
    for (int e = 0; e < EE; e++) if (e != i0 && l[e] > l[i1]) i1 = e;
    float s2 = l[i0] + l[i1];
    g_wsl[t * 2 + 0] = l[i0] / s2;
    g_wsl[t * 2 + 1] = l[i1] / s2;
    g_sel[t * 2 + 0] = i0;
    g_sel[t * 2 + 1] = i1;
    int p0 = atomicAdd(&g_cnt[i0], 1);
    g_list[i0 * BSN + p0] = t * 2;
    int p1 = atomicAdd(&g_cnt[i1], 1);
    g_list[i1 * BSN + p1] = t * 2 + 1;
}

__global__ __launch_bounds__(256) void expert_kernel(const float* __restrict__ b1,
                                                     const float* __restrict__ b3) {
    int e = blockIdx.y;
    int j0 = blockIdx.x * 256;
    __shared__ float b1s[RR][256];
    __shared__ float b3s[RR][256];
    int tid = threadIdx.x;
#pragma unroll
    for (int r = 0; r < RR; r++) {
        b1s[r][tid] = b1[((size_t)e * RR + r) * DFF + j0 + tid];
        b3s[r][tid] = b3[((size_t)e * RR + r) * DFF + j0 + tid];
    }
    __syncthreads();
    int n = g_cnt[e];
    for (int i = 0; i < n; i++) {
        int ent = g_list[e * BSN + i];
        int t = ent >> 1, slot = ent & 1;
        float x1 = g_cw1[(size_t)t * DFF + j0 + tid];
        float x3 = g_cw3[(size_t)t * DFF + j0 + tid];
        const float* m1 = &g_mid1[(size_t)t * EE * RR + e * RR];
        const float* m3 = &g_mid3[(size_t)t * EE * RR + e * RR];
#pragma unroll
        for (int r = 0; r < RR; r++) {
            x1 += SCALING_F * m1[r] * b1s[r][tid];
            x3 += SCALING_F * m3[r] * b3s[r][tid];
        }
        float sr = x1 / (1.f + expf(-x1)) * x3;
        g_srs[((size_t)t * 2 + slot) * DFF + j0 + tid] = sr;
    }
}

__global__ void combine_srw(int total) {
    int i = blockIdx.x * blockDim.x + threadIdx.x;
    if (i >= total) return;
    int t = i / DFF;
    int j = i % DFF;
    g_srw[(size_t)i] = g_wsl[t * 2 + 0] * g_srs[((size_t)t * 2 + 0) * DFF + j]
                     + g_wsl[t * 2 + 1] * g_srs[((size_t)t * 2 + 1) * DFF + j];
}

__global__ __launch_bounds__(256) void mid2_kernel(const float* __restrict__ a2) {
    int ts = blockIdx.x;
    int t = ts >> 1, slot = ts & 1;
    int e = g_sel[t * 2 + slot];
    const float* sr = g_srs + (size_t)ts * DFF;
    const float* A2 = a2 + (size_t)e * DFF * RR;
    int tid = threadIdx.x;
    int r = tid % RR;
    int jo = tid / RR;
    float acc = 0.f;
    for (int j = jo; j < DFF; j += 16) acc += sr[j] * A2[(size_t)j * RR + r];
    __shared__ float red[256];
    red[tid] = acc; __syncthreads();
    for (int s = 8; s > 0; s >>= 1) {
        if (jo < s) red[tid] += red[tid + s * RR];
        __syncthreads();
    }
    if (jo == 0) g_mid2[(size_t)ts * RR + r] = red[tid];
}

__global__ __launch_bounds__(256) void final_epilogue(const float* __restrict__ b2,
                                                      float* __restrict__ out) {
    int t = blockIdx.x;
    __shared__ float m2s[2][RR];
    __shared__ float ws[2];
    __shared__ int es[2];
    int tid = threadIdx.x;
    if (tid < 32) {
        int slot = tid / RR, r = tid % RR;
        m2s[slot][r] = g_mid2[(size_t)(t * 2 + slot) * RR + r];
    }
    if (tid < 2) { ws[tid] = g_wsl[t * 2 + tid]; es[tid] = g_sel[t * 2 + tid]; }
    __syncthreads();
    for (int d = tid; d < DD; d += 256) {
        float acc = g_x2[(size_t)t * DD + d] + g_hs[(size_t)t * DD + d];
#pragma unroll
        for (int slot = 0; slot < 2; slot++) {
            const float* B2 = b2 + (size_t)es[slot] * RR * DD;
            float c = 0.f;
#pragma unroll
            for (int r = 0; r < RR; r++) c += m2s[slot][r] * B2[(size_t)r * DD + d];
            acc += ws[slot] * SCALING_F * c;
        }
        out[(size_t)t * DD + d] = acc;
    }
}

// ---------------- launch ----------------
extern "C" void kernel_launch(void* const* d_in, const int* in_sizes, int n_in,
                              void* d_out, int out_size) {
    const float* data = (const float*)d_in[0];
    const float* cosb = (const float*)d_in[2];
    const float* sinb = (const float*)d_in[3];
    const float* anw  = (const float*)d_in[4];
    const float* fnw  = (const float*)d_in[5];
    const float* wq   = (const float*)d_in[6];
    const float* wk   = (const float*)d_in[7];
    const float* wv   = (const float*)d_in[8];
    const float* wo   = (const float*)d_in[9];
    const float* qa   = (const float*)d_in[10];
    const float* qb   = (const float*)d_in[11];
    const float* ka   = (const float*)d_in[12];
    const float* kb   = (const float*)d_in[13];
    const float* va   = (const float*)d_in[14];
    const float* vb   = (const float*)d_in[15];
    const float* oa   = (const float*)d_in[16];
    const float* ob   = (const float*)d_in[17];
    const float* gw   = (const float*)d_in[18];
    const float* w1   = (const float*)d_in[19];
    const float* w2   = (const float*)d_in[20];
    const float* w3   = (const float*)d_in[21];
    const float* a1   = (const float*)d_in[22];
    const float* b1   = (const float*)d_in[23];
    const float* a3   = (const float*)d_in[24];
    const float* b3   = (const float*)d_in[25];
    const float* a2   = (const float*)d_in[26];
    const float* b2   = (const float*)d_in[27];
    float* out = (float*)d_out;

    float *p_h, *p_tmp, *p_xq, *p_xk, *p_xv, *p_o, *p_x2, *p_sn;
    float *p_cw1, *p_cw3, *p_srw, *p_hs, *p_logits, *p_mid1, *p_mid3;
    cudaGetSymbolAddress((void**)&p_h,   g_h);
    cudaGetSymbolAddress((void**)&p_tmp, g_tmp);
    cudaGetSymbolAddress((void**)&p_xq,  g_xq);
    cudaGetSymbolAddress((void**)&p_xk,  g_xk);
    cudaGetSymbolAddress((void**)&p_xv,  g_xv);
    cudaGetSymbolAddress((void**)&p_o,   g_o);
    cudaGetSymbolAddress((void**)&p_x2,  g_x2);
    cudaGetSymbolAddress((void**)&p_sn,  g_sn);
    cudaGetSymbolAddress((void**)&p_cw1, g_cw1);
    cudaGetSymbolAddress((void**)&p_cw3, g_cw3);
    cudaGetSymbolAddress((void**)&p_srw, g_srw);
    cudaGetSymbolAddress((void**)&p_hs,  g_hs);
    cudaGetSymbolAddress((void**)&p_logits, g_logits);
    cudaGetSymbolAddress((void**)&p_mid1, g_mid1);
    cudaGetSymbolAddress((void**)&p_mid3, g_mid3);

    // 1. rmsnorm 1
    rmsnorm_kernel<<<BSN, 256>>>(data, anw, p_h);

    // 2. QKV projections (tf32 mma) + LoRA (fp32)
    tgemm_mma<<<dim3(DD/128, BSN/128), 256>>>(p_h, wq, p_xq, DD, DD, DD, DD, 0);
    skinny_gemm<16><<<dim3(BSN,1), 128>>>(p_h, qa, p_tmp, DD, DD, RR, RR, 0, 0);
    sgemm128<<<dim3(DD/128, BSN/128), 256>>>(p_tmp, qb, p_xq, RR, RR, DD, DD, SCALING_F, 1);

    tgemm_mma<<<dim3((KVHH*HDD)/128, BSN/128), 256>>>(p_h, wk, p_xk, DD, DD, KVHH*HDD, KVHH*HDD, 0);
    skinny_gemm<16><<<dim3(BSN,1), 128>>>(p_h, ka, p_tmp, DD, DD, RR, RR, 0, 0);
    sgemm128<<<dim3((KVHH*HDD)/128, BSN/128), 256>>>(p_tmp, kb, p_xk, RR, RR, KVHH*HDD, KVHH*HDD, SCALING_F, 1);

    tgemm_mma<<<dim3((KVHH*HDD)/128, BSN/128), 256>>>(p_h, wv, p_xv, DD, DD, KVHH*HDD, KVHH*HDD, 0);
    skinny_gemm<16><<<dim3(BSN,1), 128>>>(p_h, va, p_tmp, DD, DD, RR, RR, 0, 0);
    sgemm128<<<dim3((KVHH*HDD)/128, BSN/128), 256>>>(p_tmp, vb, p_xv, RR, RR, KVHH*HDD, KVHH*HDD, SCALING_F, 1);

    // 3. RoPE
    rope_kernel<<<(BSN*HH*64 + 255)/256, 256>>>(p_xq, cosb, sinb, HH, BSN*HH*64);
    rope_kernel<<<(BSN*KVHH*64 + 255)/256, 256>>>(p_xk, cosb, sinb, KVHH, BSN*KVHH*64);

    // 4. attention
    attn_scores<<<dim3(SS/64, SS/64, BB*HH), 256>>>(p_xq, p_xk);
    softmax_rows<<<BB*HH*SS, 256>>>();
    attn_av<<<dim3(HDD/64, SS/64, BB*HH), 256>>>(p_xv, p_o);

    // 5. output projection + LoRA + residual
    copy_f4<<<(BSN*DD/4 + 255)/256, 256>>>((const float4*)data, (float4*)p_x2, BSN*DD/4);
    tgemm_mma<<<dim3(DD/128, BSN/128), 256>>>(p_o, wo, p_x2, HH*HDD, HH*HDD, DD, DD, 1);
    skinny_gemm<16><<<dim3(BSN,1), 128>>>(p_o, oa, p_tmp, HH*HDD, HH*HDD, RR, RR, 0, 0);
    sgemm128<<<dim3(DD/128, BSN/128), 256>>>(p_tmp, ob, p_x2, RR, RR, DD, DD, SCALING_F, 1);

    // 6. rmsnorm 2
    rmsnorm_kernel<<<BSN, 256>>>(p_x2, fnw, p_sn);

    // 7. shared FFN GEMMs (tf32 mma)
    tgemm_mma<<<dim3(DFF/128, BSN/128), 256>>>(p_sn, w1, p_cw1, DD, DD, DFF, DFF, 0);
    tgemm_mma<<<dim3(DFF/128, BSN/128), 256>>>(p_sn, w3, p_cw3, DD, DD, DFF, DFF, 0);

    // 8. gating
    skinny_gemm<8><<<dim3(BSN,1), 128>>>(p_sn, gw, p_logits, DD, DD, EE, EE, 0, 0);
    zero_cnt_kernel<<<1, 32>>>();
    gate_topk<<<(BSN + 255)/256, 256>>>();

    // 9. per-expert LoRA mids (all experts, cheap)
    skinny_gemm<16><<<dim3(BSN, EE), 128>>>(p_sn, a1, p_mid1, DD, DD, RR, EE*RR, (long)DD*RR, RR);
    skinny_gemm<16><<<dim3(BSN, EE), 128>>>(p_sn, a3, p_mid3, DD, DD, RR, EE*RR, (long)DD*RR, RR);

    // 10. fused expert SwiGLU (selected tokens only)
    expert_kernel<<<dim3(DFF/256, EE), 256>>>(b1, b3);

    // 11. weighted combine + shared w2 GEMM (tf32 mma)
    combine_srw<<<(BSN*DFF + 255)/256, 256>>>(BSN*DFF);
    tgemm_mma<<<dim3(DD/128, BSN/128), 256>>>(p_srw, w2, p_hs, DFF, DFF, DD, DD, 0);

    // 12. lora2 mids + final epilogue
    mid2_kernel<<<BSN*2, 256>>>(a2);
    final_epilogue<<<BSN, 256>>>(b2, out);
}